// round 11
// baseline (speedup 1.0000x reference)
#include <cuda_runtime.h>
#include <cuda_bf16.h>
#include <mma.h>
#include <math.h>

using namespace nvcuda;

#define B_    32
#define H_    32
#define D_    128
#define HID_  4096
#define TH_   12288      // 3*HID
#define BS_   64
#define NBLK_ 16
#define KSPLIT 8

__device__ float g_part[KSPLIT][B_ * TH_];  // qkv partials
__device__ float g_qkv[B_ * TH_];           // [b][j]; j<4096 q, ..8191 k, .. v
__device__ float g_attn[B_ * HID_];
__device__ float g_cs[B_][64][2];           // rope cos/sin table
__device__ __nv_bfloat16 g_hhi[B_ * HID_];  // hidden split hi
__device__ __nv_bfloat16 g_hlo[B_ * HID_];  // hidden split lo

typedef unsigned long long u64;

__device__ __forceinline__ u64 fma2(u64 a, u64 b, u64 c) {
    u64 d; asm("fma.rn.f32x2 %0, %1, %2, %3;" : "=l"(d) : "l"(a), "l"(b), "l"(c)); return d;
}
__device__ __forceinline__ float lo2(u64 a) {
    float lo, hi; asm("mov.b64 {%0, %1}, %2;" : "=f"(lo), "=f"(hi) : "l"(a)); return lo;
}
__device__ __forceinline__ float hi2(u64 a) {
    float lo, hi; asm("mov.b64 {%0, %1}, %2;" : "=f"(lo), "=f"(hi) : "l"(a)); return hi;
}

// ---------------------------------------------------------------------------
// Kernel 0: split hidden into bf16 hi/lo. 131072 elts, grid 512 x 256.
// ---------------------------------------------------------------------------
__global__ __launch_bounds__(256) void hsplit_kernel(const float* __restrict__ hidden) {
    int i = blockIdx.x * 256 + threadIdx.x;
    float x = hidden[i];
    __nv_bfloat16 hi = __float2bfloat16(x);
    g_hhi[i] = hi;
    g_hlo[i] = __float2bfloat16(x - __bfloat162float(hi));
}

// ---------------------------------------------------------------------------
// Kernel 1: qkv via split-bf16 WMMA.  grid (96 j-tiles, KSPLIT=8), block 256.
// Block = 32(batch) x 128(j) tile, k-chunk 512. Per 32-k phase: stage W
// fp32->(hi,lo) bf16 in smem; warp = one 16-col n-tile, 2 m-tiles,
// 3 mma per (m, k-tile): hi@Whi + lo@Whi + hi@Wlo.
// ---------------------------------------------------------------------------
__global__ __launch_bounds__(256) void qkv_wmma_kernel(const float* __restrict__ W) {
    __shared__ __nv_bfloat16 s_whi[32][136];
    __shared__ __nv_bfloat16 s_wlo[32][136];
    const int wid = threadIdx.x >> 5;
    const int j0  = blockIdx.x * 128;
    const int k0  = blockIdx.y * (HID_ / KSPLIT);   // 512

    wmma::fragment<wmma::accumulator, 16, 16, 16, float> acc0, acc1;
    wmma::fill_fragment(acc0, 0.f);
    wmma::fill_fragment(acc1, 0.f);

    for (int ph = 0; ph < 16; ph++) {
        __syncthreads();
#pragma unroll
        for (int t = 0; t < 4; t++) {
            int idx = threadIdx.x + t * 256;
            int row = idx >> 5;
            int col = (idx & 31) * 4;
            float4 w4 = *(const float4*)&W[(size_t)(k0 + ph * 32 + row) * TH_ + j0 + col];
            __nv_bfloat16 h0 = __float2bfloat16(w4.x);
            __nv_bfloat16 h1 = __float2bfloat16(w4.y);
            __nv_bfloat16 h2 = __float2bfloat16(w4.z);
            __nv_bfloat16 h3 = __float2bfloat16(w4.w);
            s_whi[row][col + 0] = h0;
            s_whi[row][col + 1] = h1;
            s_whi[row][col + 2] = h2;
            s_whi[row][col + 3] = h3;
            s_wlo[row][col + 0] = __float2bfloat16(w4.x - __bfloat162float(h0));
            s_wlo[row][col + 1] = __float2bfloat16(w4.y - __bfloat162float(h1));
            s_wlo[row][col + 2] = __float2bfloat16(w4.z - __bfloat162float(h2));
            s_wlo[row][col + 3] = __float2bfloat16(w4.w - __bfloat162float(h3));
        }
        __syncthreads();

#pragma unroll
        for (int kt = 0; kt < 2; kt++) {
            int kg = k0 + ph * 32 + kt * 16;
            wmma::fragment<wmma::matrix_a, 16, 16, 16, __nv_bfloat16, wmma::row_major> ahi0, alo0, ahi1, alo1;
            wmma::fragment<wmma::matrix_b, 16, 16, 16, __nv_bfloat16, wmma::row_major> bhi, blo;
            wmma::load_matrix_sync(ahi0, &g_hhi[kg], HID_);
            wmma::load_matrix_sync(alo0, &g_hlo[kg], HID_);
            wmma::load_matrix_sync(ahi1, &g_hhi[16 * HID_ + kg], HID_);
            wmma::load_matrix_sync(alo1, &g_hlo[16 * HID_ + kg], HID_);
            wmma::load_matrix_sync(bhi, &s_whi[kt * 16][wid * 16], 136);
            wmma::load_matrix_sync(blo, &s_wlo[kt * 16][wid * 16], 136);
            wmma::mma_sync(acc0, ahi0, bhi, acc0);
            wmma::mma_sync(acc1, ahi1, bhi, acc1);
            wmma::mma_sync(acc0, alo0, bhi, acc0);
            wmma::mma_sync(acc1, alo1, bhi, acc1);
            wmma::mma_sync(acc0, ahi0, blo, acc0);
            wmma::mma_sync(acc1, ahi1, blo, acc1);
        }
    }

    float* outp = &g_part[blockIdx.y][0];
    wmma::store_matrix_sync(&outp[j0 + wid * 16], acc0, TH_, wmma::mem_row_major);
    wmma::store_matrix_sync(&outp[(size_t)16 * TH_ + j0 + wid * 16], acc1, TH_, wmma::mem_row_major);
}

// Reduce KSPLIT partials -> g_qkv. grid 384, block 256, float4 per thread.
__global__ __launch_bounds__(256) void qkv_reduce_kernel(int dummy) {
    int i = (blockIdx.x * 256 + threadIdx.x) * 4;
    float4 r = *(const float4*)&g_part[0][i];
#pragma unroll
    for (int p = 1; p < KSPLIT; p++) {
        float4 a = *(const float4*)&g_part[p][i];
        r.x += a.x; r.y += a.y; r.z += a.z; r.w += a.w;
    }
    *(float4*)&g_qkv[i] = r;
}

// ---------------------------------------------------------------------------
__global__ __launch_bounds__(64) void rope_table(const int* __restrict__ hist) {
    const int b = blockIdx.x;
    const int i = threadIdx.x;
    double invd = exp(-(double)i / 64.0 * 9.210340371976184);  // ln(10000)
    double angd = fmod((double)hist[b] * invd, 6.283185307179586476925286766559);
    g_cs[b][i][0] = cosf((float)angd);
    g_cs[b][i][1] = sinf((float)angd);
}

__global__ __launch_bounds__(128) void rope_apply(int dummy) {
    const int b    = blockIdx.x;
    const int part = blockIdx.y >> 5;
    const int h    = blockIdx.y & 31;
    const int d    = threadIdx.x;
    const float c = g_cs[b][d & 63][0];
    const float s = g_cs[b][d & 63][1];

    float* p = &g_qkv[b * TH_ + part * HID_ + h * D_];
    float x  = p[d];
    float xr = (d < 64) ? -p[d + 64] : p[d - 64];
    __syncthreads();
    p[d] = x * c + xr * s;
}

// ---------------------------------------------------------------------------
// Kernel 3: attention, two-phase (R10). grid = B*H blocks, 256 threads.
// ---------------------------------------------------------------------------
__global__ __launch_bounds__(256) void attn_kernel(const float* __restrict__ kcache,
                                                   const float* __restrict__ vcache,
                                                   const int* __restrict__ hist,
                                                   const int* __restrict__ boff) {
    const int b = blockIdx.x >> 5;
    const int h = blockIdx.x & 31;
    const int tid  = threadIdx.x;
    const int lane = tid & 31;
    const int wid  = tid >> 5;

    __shared__ int   s_blk[NBLK_];
    __shared__ float s_sc[1024];
    __shared__ float s_red[8];
    __shared__ float s_acc[8][128];

    if (tid < NBLK_) s_blk[tid] = boff[b * NBLK_ + tid];
    __syncthreads();

    const int pos = hist[b];
    const float scale = 0.08838834764831845f;  // 1/sqrt(128)
    const float4 q4 = *(const float4*)&g_qkv[b * TH_ + h * D_ + lane * 4];

    // ---- phase 1: scores ----
    float mloc = -1e30f;
    int s = wid;
    for (; s + 24 < pos; s += 32) {
        float4 k[4];
        int    sp[4];
#pragma unroll
        for (int u = 0; u < 4; u++) {
            sp[u] = s + u * 8;
            int a = ((s_blk[sp[u] >> 6] * BS_ + (sp[u] & 63)) * H_ + h) * D_;
            k[u] = *(const float4*)&kcache[a + lane * 4];
        }
        float dt[4];
#pragma unroll
        for (int u = 0; u < 4; u++)
            dt[u] = q4.x * k[u].x + q4.y * k[u].y + q4.z * k[u].z + q4.w * k[u].w;
#pragma unroll
        for (int o = 16; o > 0; o >>= 1)
#pragma unroll
            for (int u = 0; u < 4; u++)
                dt[u] += __shfl_xor_sync(0xffffffffu, dt[u], o);
#pragma unroll
        for (int u = 0; u < 4; u++) {
            dt[u] *= scale;
            mloc = fmaxf(mloc, dt[u]);
            if (lane == 0) s_sc[sp[u]] = dt[u];
        }
    }
    for (; s < pos; s += 8) {
        int a0 = ((s_blk[s >> 6] * BS_ + (s & 63)) * H_ + h) * D_;
        float4 k0 = *(const float4*)&kcache[a0 + lane * 4];
        float d0 = q4.x * k0.x + q4.y * k0.y + q4.z * k0.z + q4.w * k0.w;
#pragma unroll
        for (int o = 16; o > 0; o >>= 1) d0 += __shfl_xor_sync(0xffffffffu, d0, o);
        d0 *= scale;
        mloc = fmaxf(mloc, d0);
        if (lane == 0) s_sc[s] = d0;
    }
    if ((pos & 7) == wid) {      // fresh k at s == pos (ref writes cache first)
        const float* kp = &g_qkv[b * TH_ + HID_ + h * D_];
        float4 k0 = *(const float4*)&kp[lane * 4];
        float d0 = q4.x * k0.x + q4.y * k0.y + q4.z * k0.z + q4.w * k0.w;
#pragma unroll
        for (int o = 16; o > 0; o >>= 1) d0 += __shfl_xor_sync(0xffffffffu, d0, o);
        d0 *= scale;
        mloc = fmaxf(mloc, d0);
        if (lane == 0) s_sc[pos] = d0;
    }

    if (lane == 0) s_red[wid] = mloc;
    __syncthreads();
    float M = -1e30f;
#pragma unroll
    for (int w = 0; w < 8; w++) M = fmaxf(M, s_red[w]);

    float lsum = 0.f;
    for (int i = tid; i <= pos; i += 256) {
        float p = __expf(s_sc[i] - M);
        s_sc[i] = p;
        lsum += p;
    }
#pragma unroll
    for (int o = 16; o > 0; o >>= 1) lsum += __shfl_xor_sync(0xffffffffu, lsum, o);
    __syncthreads();
    if (lane == 0) s_red[wid] = lsum;
    __syncthreads();
    float L = 0.f;
#pragma unroll
    for (int w = 0; w < 8; w++) L += s_red[w];
    const float invL = 1.f / L;

    // ---- phase 2: warp = position stripe, lane = d-quad, LDG.128 ----
    float4 a4 = make_float4(0.f, 0.f, 0.f, 0.f);
    s = wid;
    for (; s + 24 < pos; s += 32) {
        float4 v[4];
        float  pr[4];
#pragma unroll
        for (int u = 0; u < 4; u++) {
            int su = s + u * 8;
            int a  = ((s_blk[su >> 6] * BS_ + (su & 63)) * H_ + h) * D_;
            v[u]  = *(const float4*)&vcache[a + lane * 4];
            pr[u] = s_sc[su];
        }
#pragma unroll
        for (int u = 0; u < 4; u++) {
            a4.x += pr[u] * v[u].x;
            a4.y += pr[u] * v[u].y;
            a4.z += pr[u] * v[u].z;
            a4.w += pr[u] * v[u].w;
        }
    }
    for (; s < pos; s += 8) {
        int a = ((s_blk[s >> 6] * BS_ + (s & 63)) * H_ + h) * D_;
        float4 v = *(const float4*)&vcache[a + lane * 4];
        float  p = s_sc[s];
        a4.x += p * v.x; a4.y += p * v.y; a4.z += p * v.z; a4.w += p * v.w;
    }
    if ((pos & 7) == wid) {      // fresh v at s == pos
        const float* vp = &g_qkv[b * TH_ + 2 * HID_ + h * D_];
        float4 v = *(const float4*)&vp[lane * 4];
        float  p = s_sc[pos];
        a4.x += p * v.x; a4.y += p * v.y; a4.z += p * v.z; a4.w += p * v.w;
    }

    *(float4*)&s_acc[wid][lane * 4] = a4;
    __syncthreads();
    if (tid < 128) {
        float val = 0.f;
#pragma unroll
        for (int w = 0; w < 8; w++) val += s_acc[w][tid];
        g_attn[b * HID_ + h * D_ + tid] = val * invL;
    }
}

// ---------------------------------------------------------------------------
// Kernel 4: out = attn @ Wo^T, f32x2 (R10). block 128, warp = 2 rows x 16 b.
// ---------------------------------------------------------------------------
__global__ __launch_bounds__(128) void oproj_kernel(const float* __restrict__ Wo,
                                                    float* __restrict__ out) {
    __shared__ float s_attn[16][256];
    const int lane = threadIdx.x & 31;
    const int wid  = threadIdx.x >> 5;
    const int tile = blockIdx.x >> 1;
    const int bh   = (blockIdx.x & 1) * 16;
    const int i0   = tile * 8 + wid * 2;

    u64 acc[2][16];
#pragma unroll
    for (int r = 0; r < 2; r++)
#pragma unroll
        for (int b = 0; b < 16; b++) acc[r][b] = 0ull;

    for (int jt = 0; jt < HID_; jt += 256) {
        __syncthreads();
#pragma unroll
        for (int t = 0; t < 8; t++) {
            int idx = threadIdx.x + t * 128;
            int b   = idx >> 6;
            int jj  = (idx & 63) << 2;
            *(float4*)&s_attn[b][jj] = *(const float4*)&g_attn[(bh + b) * HID_ + jt + jj];
        }
        __syncthreads();

        const float* w = Wo + (size_t)i0 * HID_ + jt;
#pragma unroll
        for (int part = 0; part < 2; part++) {
            int j0 = part * 128 + lane * 4;
            ulonglong2 w0 = *(const ulonglong2*)&w[j0];
            ulonglong2 w1 = *(const ulonglong2*)&w[HID_ + j0];
#pragma unroll
            for (int b = 0; b < 16; b++) {
                ulonglong2 a = *(const ulonglong2*)&s_attn[b][j0];
                acc[0][b] = fma2(a.x, w0.x, acc[0][b]);
                acc[0][b] = fma2(a.y, w0.y, acc[0][b]);
                acc[1][b] = fma2(a.x, w1.x, acc[1][b]);
                acc[1][b] = fma2(a.y, w1.y, acc[1][b]);
            }
        }
    }

#pragma unroll
    for (int r = 0; r < 2; r++) {
        float res = 0.f;
#pragma unroll
        for (int b = 0; b < 16; b++) {
            float v = lo2(acc[r][b]) + hi2(acc[r][b]);
#pragma unroll
            for (int o = 16; o > 0; o >>= 1) v += __shfl_xor_sync(0xffffffffu, v, o);
            if (lane == b) res = v;
        }
        if (lane < 16) out[(bh + lane) * HID_ + i0 + r] = res;
    }
}

// ---------------------------------------------------------------------------
extern "C" void kernel_launch(void* const* d_in, const int* in_sizes, int n_in,
                              void* d_out, int out_size) {
    const float* hidden = (const float*)d_in[0];
    const float* W      = (const float*)d_in[1];
    const float* Wo     = (const float*)d_in[2];
    const float* kcache = (const float*)d_in[3];
    const float* vcache = (const float*)d_in[4];
    const int*   hist   = (const int*)d_in[5];
    const int*   boff   = (const int*)d_in[6];
    float*       out    = (float*)d_out;

    hsplit_kernel<<<B_ * HID_ / 256, 256>>>(hidden);
    qkv_wmma_kernel<<<dim3(TH_ / 128, KSPLIT), 256>>>(W);
    qkv_reduce_kernel<<<B_ * TH_ / 1024, 256>>>(0);
    rope_table<<<B_, 64>>>(hist);
    rope_apply<<<dim3(B_, 2 * H_), 128>>>(0);
    attn_kernel<<<B_ * H_, 256>>>(kcache, vcache, hist, boff);
    oproj_kernel<<<1024, 128>>>(Wo, out);
}

// round 12
// speedup vs baseline: 1.2546x; 1.2546x over previous
#include <cuda_runtime.h>
#include <cuda_bf16.h>
#include <mma.h>
#include <math.h>

using namespace nvcuda;

#define B_    32
#define H_    32
#define D_    128
#define HID_  4096
#define TH_   12288      // 3*HID
#define BS_   64
#define NBLK_ 16
#define KSPLIT 8

__device__ float g_part[KSPLIT][B_ * TH_];  // qkv partials
__device__ float g_qkv[B_ * TH_];           // [b][j]; j<4096 q, ..8191 k, .. v
__device__ float g_attn[B_ * HID_];
__device__ float g_cs[B_][64][2];           // rope cos/sin table
__device__ __nv_bfloat16 g_hhi[B_ * HID_];  // hidden split hi
__device__ __nv_bfloat16 g_hlo[B_ * HID_];  // hidden split lo

typedef unsigned long long u64;

__device__ __forceinline__ u64 fma2(u64 a, u64 b, u64 c) {
    u64 d; asm("fma.rn.f32x2 %0, %1, %2, %3;" : "=l"(d) : "l"(a), "l"(b), "l"(c)); return d;
}
__device__ __forceinline__ float lo2(u64 a) {
    float lo, hi; asm("mov.b64 {%0, %1}, %2;" : "=f"(lo), "=f"(hi) : "l"(a)); return lo;
}
__device__ __forceinline__ float hi2(u64 a) {
    float lo, hi; asm("mov.b64 {%0, %1}, %2;" : "=f"(lo), "=f"(hi) : "l"(a)); return hi;
}

// ---------------------------------------------------------------------------
// Kernel 0: split hidden into bf16 hi/lo. 131072 elts.
// ---------------------------------------------------------------------------
__global__ __launch_bounds__(256) void hsplit_kernel(const float* __restrict__ hidden) {
    int i = blockIdx.x * 256 + threadIdx.x;
    float x = hidden[i];
    __nv_bfloat16 hi = __float2bfloat16(x);
    g_hhi[i] = hi;
    g_hlo[i] = __float2bfloat16(x - __bfloat162float(hi));
}

// ---------------------------------------------------------------------------
// Kernel 1: qkv via split-bf16 WMMA, smem-staged A + W-register prefetch.
// grid (96 j-tiles, KSPLIT=8), block 256 = 8 warps.
// Block = 32(batch) x 128(j); k-chunk 512 in 16 phases of 32.
// Per phase: stage W(fp32->hi/lo bf16) + A(hi/lo) in smem; warp = 16-col
// j-tile, 2 m-tiles, 2 k-tiles x 3 split-MMAs; next-phase W LDGs in flight.
// ---------------------------------------------------------------------------
__global__ __launch_bounds__(256) void qkv_wmma_kernel(const float* __restrict__ W) {
    __shared__ __nv_bfloat16 s_whi[32][136];
    __shared__ __nv_bfloat16 s_wlo[32][136];
    __shared__ __nv_bfloat16 s_ahi[32][40];
    __shared__ __nv_bfloat16 s_alo[32][40];
    const int tid = threadIdx.x;
    const int wid = tid >> 5;
    const int j0  = blockIdx.x * 128;
    const int k0  = blockIdx.y * (HID_ / KSPLIT);   // 512

    wmma::fragment<wmma::accumulator, 16, 16, 16, float> acc0, acc1;
    wmma::fill_fragment(acc0, 0.f);
    wmma::fill_fragment(acc1, 0.f);

    const float* wbase = W + j0;
    const int wrow = tid >> 5;           // reuse: staging row per t computed below
    (void)wrow;

    float4 wreg[4];
#pragma unroll
    for (int t = 0; t < 4; t++) {
        int idx = tid + t * 256;
        wreg[t] = *(const float4*)&wbase[(size_t)(k0 + (idx >> 5)) * TH_ + (idx & 31) * 4];
    }

    // A staging address (constant per thread across phases except k offset)
    const __nv_bfloat16* asrc = (tid < 128) ? g_hhi : g_hlo;
    __nv_bfloat16* adst = (tid < 128) ? &s_ahi[0][0] : &s_alo[0][0];
    const int ai   = tid & 127;
    const int arow = ai >> 2;
    const int acol = (ai & 3) * 8;

    for (int ph = 0; ph < 16; ph++) {
        uint4 areg = *(const uint4*)&asrc[arow * HID_ + k0 + ph * 32 + acol];
        __syncthreads();                       // prior phase's MMAs done
        // stage W: convert fp32 -> (hi, lo) bf16
#pragma unroll
        for (int t = 0; t < 4; t++) {
            int idx = tid + t * 256;
            int row = idx >> 5;
            int col = (idx & 31) * 4;
            float4 w4 = wreg[t];
            __nv_bfloat16 h0 = __float2bfloat16(w4.x);
            __nv_bfloat16 h1 = __float2bfloat16(w4.y);
            __nv_bfloat16 h2 = __float2bfloat16(w4.z);
            __nv_bfloat16 h3 = __float2bfloat16(w4.w);
            s_whi[row][col + 0] = h0;
            s_whi[row][col + 1] = h1;
            s_whi[row][col + 2] = h2;
            s_whi[row][col + 3] = h3;
            s_wlo[row][col + 0] = __float2bfloat16(w4.x - __bfloat162float(h0));
            s_wlo[row][col + 1] = __float2bfloat16(w4.y - __bfloat162float(h1));
            s_wlo[row][col + 2] = __float2bfloat16(w4.z - __bfloat162float(h2));
            s_wlo[row][col + 3] = __float2bfloat16(w4.w - __bfloat162float(h3));
        }
        *(uint4*)&adst[arow * 40 + acol] = areg;
        __syncthreads();

        if (ph + 1 < 16) {                     // next-phase W LDGs in flight
#pragma unroll
            for (int t = 0; t < 4; t++) {
                int idx = tid + t * 256;
                wreg[t] = *(const float4*)&wbase[(size_t)(k0 + (ph + 1) * 32 + (idx >> 5)) * TH_ + (idx & 31) * 4];
            }
        }

#pragma unroll
        for (int kt = 0; kt < 2; kt++) {
            wmma::fragment<wmma::matrix_a, 16, 16, 16, __nv_bfloat16, wmma::row_major> ahi0, alo0, ahi1, alo1;
            wmma::fragment<wmma::matrix_b, 16, 16, 16, __nv_bfloat16, wmma::row_major> bhi, blo;
            wmma::load_matrix_sync(ahi0, &s_ahi[0][kt * 16], 40);
            wmma::load_matrix_sync(ahi1, &s_ahi[16][kt * 16], 40);
            wmma::load_matrix_sync(alo0, &s_alo[0][kt * 16], 40);
            wmma::load_matrix_sync(alo1, &s_alo[16][kt * 16], 40);
            wmma::load_matrix_sync(bhi, &s_whi[kt * 16][wid * 16], 136);
            wmma::load_matrix_sync(blo, &s_wlo[kt * 16][wid * 16], 136);
            wmma::mma_sync(acc0, ahi0, bhi, acc0);
            wmma::mma_sync(acc1, ahi1, bhi, acc1);
            wmma::mma_sync(acc0, alo0, bhi, acc0);
            wmma::mma_sync(acc1, alo1, bhi, acc1);
            wmma::mma_sync(acc0, ahi0, blo, acc0);
            wmma::mma_sync(acc1, ahi1, blo, acc1);
        }
    }

    float* outp = &g_part[blockIdx.y][0];
    wmma::store_matrix_sync(&outp[j0 + wid * 16], acc0, TH_, wmma::mem_row_major);
    wmma::store_matrix_sync(&outp[(size_t)16 * TH_ + j0 + wid * 16], acc1, TH_, wmma::mem_row_major);
}

// Reduce KSPLIT partials -> g_qkv. grid 384, block 256, float4 per thread.
__global__ __launch_bounds__(256) void qkv_reduce_kernel(int dummy) {
    int i = (blockIdx.x * 256 + threadIdx.x) * 4;
    float4 r = *(const float4*)&g_part[0][i];
#pragma unroll
    for (int p = 1; p < KSPLIT; p++) {
        float4 a = *(const float4*)&g_part[p][i];
        r.x += a.x; r.y += a.y; r.z += a.z; r.w += a.w;
    }
    *(float4*)&g_qkv[i] = r;
}

// ---------------------------------------------------------------------------
__global__ __launch_bounds__(64) void rope_table(const int* __restrict__ hist) {
    const int b = blockIdx.x;
    const int i = threadIdx.x;
    double invd = exp(-(double)i / 64.0 * 9.210340371976184);  // ln(10000)
    double angd = fmod((double)hist[b] * invd, 6.283185307179586476925286766559);
    g_cs[b][i][0] = cosf((float)angd);
    g_cs[b][i][1] = sinf((float)angd);
}

__global__ __launch_bounds__(128) void rope_apply(int dummy) {
    const int b    = blockIdx.x;
    const int part = blockIdx.y >> 5;
    const int h    = blockIdx.y & 31;
    const int d    = threadIdx.x;
    const float c = g_cs[b][d & 63][0];
    const float s = g_cs[b][d & 63][1];

    float* p = &g_qkv[b * TH_ + part * HID_ + h * D_];
    float x  = p[d];
    float xr = (d < 64) ? -p[d + 64] : p[d - 64];
    __syncthreads();
    p[d] = x * c + xr * s;
}

// ---------------------------------------------------------------------------
// Kernel 3: attention, two-phase (R10). grid = B*H blocks, 256 threads.
// ---------------------------------------------------------------------------
__global__ __launch_bounds__(256) void attn_kernel(const float* __restrict__ kcache,
                                                   const float* __restrict__ vcache,
                                                   const int* __restrict__ hist,
                                                   const int* __restrict__ boff) {
    const int b = blockIdx.x >> 5;
    const int h = blockIdx.x & 31;
    const int tid  = threadIdx.x;
    const int lane = tid & 31;
    const int wid  = tid >> 5;

    __shared__ int   s_blk[NBLK_];
    __shared__ float s_sc[1024];
    __shared__ float s_red[8];
    __shared__ float s_acc[8][128];

    if (tid < NBLK_) s_blk[tid] = boff[b * NBLK_ + tid];
    __syncthreads();

    const int pos = hist[b];
    const float scale = 0.08838834764831845f;  // 1/sqrt(128)
    const float4 q4 = *(const float4*)&g_qkv[b * TH_ + h * D_ + lane * 4];

    // ---- phase 1: scores ----
    float mloc = -1e30f;
    int s = wid;
    for (; s + 24 < pos; s += 32) {
        float4 k[4];
        int    sp[4];
#pragma unroll
        for (int u = 0; u < 4; u++) {
            sp[u] = s + u * 8;
            int a = ((s_blk[sp[u] >> 6] * BS_ + (sp[u] & 63)) * H_ + h) * D_;
            k[u] = *(const float4*)&kcache[a + lane * 4];
        }
        float dt[4];
#pragma unroll
        for (int u = 0; u < 4; u++)
            dt[u] = q4.x * k[u].x + q4.y * k[u].y + q4.z * k[u].z + q4.w * k[u].w;
#pragma unroll
        for (int o = 16; o > 0; o >>= 1)
#pragma unroll
            for (int u = 0; u < 4; u++)
                dt[u] += __shfl_xor_sync(0xffffffffu, dt[u], o);
#pragma unroll
        for (int u = 0; u < 4; u++) {
            dt[u] *= scale;
            mloc = fmaxf(mloc, dt[u]);
            if (lane == 0) s_sc[sp[u]] = dt[u];
        }
    }
    for (; s < pos; s += 8) {
        int a0 = ((s_blk[s >> 6] * BS_ + (s & 63)) * H_ + h) * D_;
        float4 k0 = *(const float4*)&kcache[a0 + lane * 4];
        float d0 = q4.x * k0.x + q4.y * k0.y + q4.z * k0.z + q4.w * k0.w;
#pragma unroll
        for (int o = 16; o > 0; o >>= 1) d0 += __shfl_xor_sync(0xffffffffu, d0, o);
        d0 *= scale;
        mloc = fmaxf(mloc, d0);
        if (lane == 0) s_sc[s] = d0;
    }
    if ((pos & 7) == wid) {      // fresh k at s == pos (ref writes cache first)
        const float* kp = &g_qkv[b * TH_ + HID_ + h * D_];
        float4 k0 = *(const float4*)&kp[lane * 4];
        float d0 = q4.x * k0.x + q4.y * k0.y + q4.z * k0.z + q4.w * k0.w;
#pragma unroll
        for (int o = 16; o > 0; o >>= 1) d0 += __shfl_xor_sync(0xffffffffu, d0, o);
        d0 *= scale;
        mloc = fmaxf(mloc, d0);
        if (lane == 0) s_sc[pos] = d0;
    }

    if (lane == 0) s_red[wid] = mloc;
    __syncthreads();
    float M = -1e30f;
#pragma unroll
    for (int w = 0; w < 8; w++) M = fmaxf(M, s_red[w]);

    float lsum = 0.f;
    for (int i = tid; i <= pos; i += 256) {
        float p = __expf(s_sc[i] - M);
        s_sc[i] = p;
        lsum += p;
    }
#pragma unroll
    for (int o = 16; o > 0; o >>= 1) lsum += __shfl_xor_sync(0xffffffffu, lsum, o);
    __syncthreads();
    if (lane == 0) s_red[wid] = lsum;
    __syncthreads();
    float L = 0.f;
#pragma unroll
    for (int w = 0; w < 8; w++) L += s_red[w];
    const float invL = 1.f / L;

    // ---- phase 2: warp = position stripe, lane = d-quad, LDG.128 ----
    float4 a4 = make_float4(0.f, 0.f, 0.f, 0.f);
    s = wid;
    for (; s + 24 < pos; s += 32) {
        float4 v[4];
        float  pr[4];
#pragma unroll
        for (int u = 0; u < 4; u++) {
            int su = s + u * 8;
            int a  = ((s_blk[su >> 6] * BS_ + (su & 63)) * H_ + h) * D_;
            v[u]  = *(const float4*)&vcache[a + lane * 4];
            pr[u] = s_sc[su];
        }
#pragma unroll
        for (int u = 0; u < 4; u++) {
            a4.x += pr[u] * v[u].x;
            a4.y += pr[u] * v[u].y;
            a4.z += pr[u] * v[u].z;
            a4.w += pr[u] * v[u].w;
        }
    }
    for (; s < pos; s += 8) {
        int a = ((s_blk[s >> 6] * BS_ + (s & 63)) * H_ + h) * D_;
        float4 v = *(const float4*)&vcache[a + lane * 4];
        float  p = s_sc[s];
        a4.x += p * v.x; a4.y += p * v.y; a4.z += p * v.z; a4.w += p * v.w;
    }
    if ((pos & 7) == wid) {      // fresh v at s == pos
        const float* vp = &g_qkv[b * TH_ + 2 * HID_ + h * D_];
        float4 v = *(const float4*)&vp[lane * 4];
        float  p = s_sc[pos];
        a4.x += p * v.x; a4.y += p * v.y; a4.z += p * v.z; a4.w += p * v.w;
    }

    *(float4*)&s_acc[wid][lane * 4] = a4;
    __syncthreads();
    if (tid < 128) {
        float val = 0.f;
#pragma unroll
        for (int w = 0; w < 8; w++) val += s_acc[w][tid];
        g_attn[b * HID_ + h * D_ + tid] = val * invL;
    }
}

// ---------------------------------------------------------------------------
// Kernel 4: out = attn @ Wo^T, f32x2 (R10). block 128, warp = 2 rows x 16 b.
// ---------------------------------------------------------------------------
__global__ __launch_bounds__(128) void oproj_kernel(const float* __restrict__ Wo,
                                                    float* __restrict__ out) {
    __shared__ float s_attn[16][256];
    const int lane = threadIdx.x & 31;
    const int wid  = threadIdx.x >> 5;
    const int tile = blockIdx.x >> 1;
    const int bh   = (blockIdx.x & 1) * 16;
    const int i0   = tile * 8 + wid * 2;

    u64 acc[2][16];
#pragma unroll
    for (int r = 0; r < 2; r++)
#pragma unroll
        for (int b = 0; b < 16; b++) acc[r][b] = 0ull;

    for (int jt = 0; jt < HID_; jt += 256) {
        __syncthreads();
#pragma unroll
        for (int t = 0; t < 8; t++) {
            int idx = threadIdx.x + t * 128;
            int b   = idx >> 6;
            int jj  = (idx & 63) << 2;
            *(float4*)&s_attn[b][jj] = *(const float4*)&g_attn[(bh + b) * HID_ + jt + jj];
        }
        __syncthreads();

        const float* w = Wo + (size_t)i0 * HID_ + jt;
#pragma unroll
        for (int part = 0; part < 2; part++) {
            int j0 = part * 128 + lane * 4;
            ulonglong2 w0 = *(const ulonglong2*)&w[j0];
            ulonglong2 w1 = *(const ulonglong2*)&w[HID_ + j0];
#pragma unroll
            for (int b = 0; b < 16; b++) {
                ulonglong2 a = *(const ulonglong2*)&s_attn[b][j0];
                acc[0][b] = fma2(a.x, w0.x, acc[0][b]);
                acc[0][b] = fma2(a.y, w0.y, acc[0][b]);
                acc[1][b] = fma2(a.x, w1.x, acc[1][b]);
                acc[1][b] = fma2(a.y, w1.y, acc[1][b]);
            }
        }
    }

#pragma unroll
    for (int r = 0; r < 2; r++) {
        float res = 0.f;
#pragma unroll
        for (int b = 0; b < 16; b++) {
            float v = lo2(acc[r][b]) + hi2(acc[r][b]);
#pragma unroll
            for (int o = 16; o > 0; o >>= 1) v += __shfl_xor_sync(0xffffffffu, v, o);
            if (lane == b) res = v;
        }
        if (lane < 16) out[(bh + lane) * HID_ + i0 + r] = res;
    }
}

// ---------------------------------------------------------------------------
extern "C" void kernel_launch(void* const* d_in, const int* in_sizes, int n_in,
                              void* d_out, int out_size) {
    const float* hidden = (const float*)d_in[0];
    const float* W      = (const float*)d_in[1];
    const float* Wo     = (const float*)d_in[2];
    const float* kcache = (const float*)d_in[3];
    const float* vcache = (const float*)d_in[4];
    const int*   hist   = (const int*)d_in[5];
    const int*   boff   = (const int*)d_in[6];
    float*       out    = (float*)d_out;

    hsplit_kernel<<<B_ * HID_ / 256, 256>>>(hidden);
    qkv_wmma_kernel<<<dim3(TH_ / 128, KSPLIT), 256>>>(W);
    qkv_reduce_kernel<<<B_ * TH_ / 1024, 256>>>(0);
    rope_table<<<B_, 64>>>(hist);
    rope_apply<<<dim3(B_, 2 * H_), 128>>>(0);
    attn_kernel<<<B_ * H_, 256>>>(kcache, vcache, hist, boff);
    oproj_kernel<<<1024, 128>>>(Wo, out);
}

// round 13
// speedup vs baseline: 1.4405x; 1.1482x over previous
#include <cuda_runtime.h>
#include <cuda_bf16.h>
#include <mma.h>
#include <math.h>

using namespace nvcuda;

#define B_    32
#define H_    32
#define D_    128
#define HID_  4096
#define TH_   12288      // 3*HID
#define BS_   64
#define NBLK_ 16
#define KSPLIT 8
#define KSPLITO 4

__device__ float g_part[KSPLIT][B_ * TH_];  // qkv partials (also reused by oproj)
__device__ float g_qkv[B_ * TH_];           // [b][j]; j<4096 q, ..8191 k, .. v
__device__ float g_cs[B_][64][2];           // rope cos/sin table
__device__ __nv_bfloat16 g_hhi[B_ * HID_];  // hidden split hi
__device__ __nv_bfloat16 g_hlo[B_ * HID_];  // hidden split lo
__device__ __nv_bfloat16 g_ahi[B_ * HID_];  // attn split hi
__device__ __nv_bfloat16 g_alo[B_ * HID_];  // attn split lo

// ---------------------------------------------------------------------------
// Kernel 0: split hidden into bf16 hi/lo; blocks 0-31 also fill rope table.
// ---------------------------------------------------------------------------
__global__ __launch_bounds__(256) void hsplit_kernel(const float* __restrict__ hidden,
                                                     const int* __restrict__ hist) {
    int i = blockIdx.x * 256 + threadIdx.x;
    float x = hidden[i];
    __nv_bfloat16 hi = __float2bfloat16(x);
    g_hhi[i] = hi;
    g_hlo[i] = __float2bfloat16(x - __bfloat162float(hi));

    if (blockIdx.x < 32 && threadIdx.x < 64) {
        const int b = blockIdx.x;
        const int f = threadIdx.x;
        double invd = exp(-(double)f / 64.0 * 9.210340371976184);  // ln(10000)
        double angd = fmod((double)hist[b] * invd, 6.283185307179586476925286766559);
        g_cs[b][f][0] = cosf((float)angd);
        g_cs[b][f][1] = sinf((float)angd);
    }
}

// ---------------------------------------------------------------------------
// Kernel 1: qkv via split-bf16 WMMA (R12, proven). grid (96, KSPLIT=8), blk 256.
// ---------------------------------------------------------------------------
__global__ __launch_bounds__(256) void qkv_wmma_kernel(const float* __restrict__ W) {
    __shared__ __nv_bfloat16 s_whi[32][136];
    __shared__ __nv_bfloat16 s_wlo[32][136];
    __shared__ __nv_bfloat16 s_ahi[32][40];
    __shared__ __nv_bfloat16 s_alo[32][40];
    const int tid = threadIdx.x;
    const int wid = tid >> 5;
    const int j0  = blockIdx.x * 128;
    const int k0  = blockIdx.y * (HID_ / KSPLIT);   // 512

    wmma::fragment<wmma::accumulator, 16, 16, 16, float> acc0, acc1;
    wmma::fill_fragment(acc0, 0.f);
    wmma::fill_fragment(acc1, 0.f);

    const float* wbase = W + j0;
    float4 wreg[4];
#pragma unroll
    for (int t = 0; t < 4; t++) {
        int idx = tid + t * 256;
        wreg[t] = *(const float4*)&wbase[(size_t)(k0 + (idx >> 5)) * TH_ + (idx & 31) * 4];
    }

    const __nv_bfloat16* asrc = (tid < 128) ? g_hhi : g_hlo;
    __nv_bfloat16* adst = (tid < 128) ? &s_ahi[0][0] : &s_alo[0][0];
    const int ai   = tid & 127;
    const int arow = ai >> 2;
    const int acol = (ai & 3) * 8;

    for (int ph = 0; ph < 16; ph++) {
        uint4 areg = *(const uint4*)&asrc[arow * HID_ + k0 + ph * 32 + acol];
        __syncthreads();
#pragma unroll
        for (int t = 0; t < 4; t++) {
            int idx = tid + t * 256;
            int row = idx >> 5;
            int col = (idx & 31) * 4;
            float4 w4 = wreg[t];
            __nv_bfloat16 h0 = __float2bfloat16(w4.x);
            __nv_bfloat16 h1 = __float2bfloat16(w4.y);
            __nv_bfloat16 h2 = __float2bfloat16(w4.z);
            __nv_bfloat16 h3 = __float2bfloat16(w4.w);
            s_whi[row][col + 0] = h0;
            s_whi[row][col + 1] = h1;
            s_whi[row][col + 2] = h2;
            s_whi[row][col + 3] = h3;
            s_wlo[row][col + 0] = __float2bfloat16(w4.x - __bfloat162float(h0));
            s_wlo[row][col + 1] = __float2bfloat16(w4.y - __bfloat162float(h1));
            s_wlo[row][col + 2] = __float2bfloat16(w4.z - __bfloat162float(h2));
            s_wlo[row][col + 3] = __float2bfloat16(w4.w - __bfloat162float(h3));
        }
        *(uint4*)&adst[arow * 40 + acol] = areg;
        __syncthreads();

        if (ph + 1 < 16) {
#pragma unroll
            for (int t = 0; t < 4; t++) {
                int idx = tid + t * 256;
                wreg[t] = *(const float4*)&wbase[(size_t)(k0 + (ph + 1) * 32 + (idx >> 5)) * TH_ + (idx & 31) * 4];
            }
        }

#pragma unroll
        for (int kt = 0; kt < 2; kt++) {
            wmma::fragment<wmma::matrix_a, 16, 16, 16, __nv_bfloat16, wmma::row_major> ahi0, alo0, ahi1, alo1;
            wmma::fragment<wmma::matrix_b, 16, 16, 16, __nv_bfloat16, wmma::row_major> bhi, blo;
            wmma::load_matrix_sync(ahi0, &s_ahi[0][kt * 16], 40);
            wmma::load_matrix_sync(ahi1, &s_ahi[16][kt * 16], 40);
            wmma::load_matrix_sync(alo0, &s_alo[0][kt * 16], 40);
            wmma::load_matrix_sync(alo1, &s_alo[16][kt * 16], 40);
            wmma::load_matrix_sync(bhi, &s_whi[kt * 16][wid * 16], 136);
            wmma::load_matrix_sync(blo, &s_wlo[kt * 16][wid * 16], 136);
            wmma::mma_sync(acc0, ahi0, bhi, acc0);
            wmma::mma_sync(acc1, ahi1, bhi, acc1);
            wmma::mma_sync(acc0, alo0, bhi, acc0);
            wmma::mma_sync(acc1, alo1, bhi, acc1);
            wmma::mma_sync(acc0, ahi0, blo, acc0);
            wmma::mma_sync(acc1, ahi1, blo, acc1);
        }
    }

    float* outp = &g_part[blockIdx.y][0];
    wmma::store_matrix_sync(&outp[j0 + wid * 16], acc0, TH_, wmma::mem_row_major);
    wmma::store_matrix_sync(&outp[(size_t)16 * TH_ + j0 + wid * 16], acc1, TH_, wmma::mem_row_major);
}

// ---------------------------------------------------------------------------
// Kernel 2: reduce KSPLIT partials + apply RoPE inline. grid 256 x 256.
// Threads [0,32768): q/k pairs (d, d+64); threads [32768,65536): v copy.
// ---------------------------------------------------------------------------
__global__ __launch_bounds__(256) void qkv_reduce_rope(int dummy) {
    const int t = blockIdx.x * 256 + threadIdx.x;
    if (t < 32768) {
        // pair decomposition: b(32) x part(2) x h(32) x dq(16)
        const int b    = t >> 10;
        const int rem  = t & 1023;
        const int part = rem >> 9;
        const int rem2 = rem & 511;
        const int h    = rem2 >> 4;
        const int dq   = rem2 & 15;
        const int d0   = dq * 4;                     // 0..60
        const int idx_lo = b * TH_ + part * HID_ + h * D_ + d0;
        const int idx_hi = idx_lo + 64;

        float4 rl = *(const float4*)&g_part[0][idx_lo];
        float4 rh = *(const float4*)&g_part[0][idx_hi];
#pragma unroll
        for (int p = 1; p < KSPLIT; p++) {
            float4 a = *(const float4*)&g_part[p][idx_lo];
            float4 c = *(const float4*)&g_part[p][idx_hi];
            rl.x += a.x; rl.y += a.y; rl.z += a.z; rl.w += a.w;
            rh.x += c.x; rh.y += c.y; rh.z += c.z; rh.w += c.w;
        }
        float4 cs0 = *(const float4*)&g_cs[b][d0][0];      // c0 s0 c1 s1
        float4 cs1 = *(const float4*)&g_cs[b][d0 + 2][0];  // c2 s2 c3 s3
        float4 ol, oh;
        ol.x = rl.x * cs0.x - rh.x * cs0.y;  oh.x = rh.x * cs0.x + rl.x * cs0.y;
        ol.y = rl.y * cs0.z - rh.y * cs0.w;  oh.y = rh.y * cs0.z + rl.y * cs0.w;
        ol.z = rl.z * cs1.x - rh.z * cs1.y;  oh.z = rh.z * cs1.x + rl.z * cs1.y;
        ol.w = rl.w * cs1.z - rh.w * cs1.w;  oh.w = rh.w * cs1.z + rl.w * cs1.w;
        *(float4*)&g_qkv[idx_lo] = ol;
        *(float4*)&g_qkv[idx_hi] = oh;
    } else {
        const int t2  = t - 32768;
        const int b   = t2 >> 10;
        const int off = (t2 & 1023) * 4;
        const int idx = b * TH_ + 2 * HID_ + off;
        float4 r = *(const float4*)&g_part[0][idx];
#pragma unroll
        for (int p = 1; p < KSPLIT; p++) {
            float4 a = *(const float4*)&g_part[p][idx];
            r.x += a.x; r.y += a.y; r.z += a.z; r.w += a.w;
        }
        *(float4*)&g_qkv[idx] = r;
    }
}

// ---------------------------------------------------------------------------
// Kernel 3: attention, two-phase (R10). Epilogue writes bf16 hi/lo split.
// ---------------------------------------------------------------------------
__global__ __launch_bounds__(256) void attn_kernel(const float* __restrict__ kcache,
                                                   const float* __restrict__ vcache,
                                                   const int* __restrict__ hist,
                                                   const int* __restrict__ boff) {
    const int b = blockIdx.x >> 5;
    const int h = blockIdx.x & 31;
    const int tid  = threadIdx.x;
    const int lane = tid & 31;
    const int wid  = tid >> 5;

    __shared__ int   s_blk[NBLK_];
    __shared__ float s_sc[1024];
    __shared__ float s_red[8];
    __shared__ float s_acc[8][128];

    if (tid < NBLK_) s_blk[tid] = boff[b * NBLK_ + tid];
    __syncthreads();

    const int pos = hist[b];
    const float scale = 0.08838834764831845f;  // 1/sqrt(128)
    const float4 q4 = *(const float4*)&g_qkv[b * TH_ + h * D_ + lane * 4];

    float mloc = -1e30f;
    int s = wid;
    for (; s + 24 < pos; s += 32) {
        float4 k[4];
        int    sp[4];
#pragma unroll
        for (int u = 0; u < 4; u++) {
            sp[u] = s + u * 8;
            int a = ((s_blk[sp[u] >> 6] * BS_ + (sp[u] & 63)) * H_ + h) * D_;
            k[u] = *(const float4*)&kcache[a + lane * 4];
        }
        float dt[4];
#pragma unroll
        for (int u = 0; u < 4; u++)
            dt[u] = q4.x * k[u].x + q4.y * k[u].y + q4.z * k[u].z + q4.w * k[u].w;
#pragma unroll
        for (int o = 16; o > 0; o >>= 1)
#pragma unroll
            for (int u = 0; u < 4; u++)
                dt[u] += __shfl_xor_sync(0xffffffffu, dt[u], o);
#pragma unroll
        for (int u = 0; u < 4; u++) {
            dt[u] *= scale;
            mloc = fmaxf(mloc, dt[u]);
            if (lane == 0) s_sc[sp[u]] = dt[u];
        }
    }
    for (; s < pos; s += 8) {
        int a0 = ((s_blk[s >> 6] * BS_ + (s & 63)) * H_ + h) * D_;
        float4 k0 = *(const float4*)&kcache[a0 + lane * 4];
        float d0 = q4.x * k0.x + q4.y * k0.y + q4.z * k0.z + q4.w * k0.w;
#pragma unroll
        for (int o = 16; o > 0; o >>= 1) d0 += __shfl_xor_sync(0xffffffffu, d0, o);
        d0 *= scale;
        mloc = fmaxf(mloc, d0);
        if (lane == 0) s_sc[s] = d0;
    }
    if ((pos & 7) == wid) {
        const float* kp = &g_qkv[b * TH_ + HID_ + h * D_];
        float4 k0 = *(const float4*)&kp[lane * 4];
        float d0 = q4.x * k0.x + q4.y * k0.y + q4.z * k0.z + q4.w * k0.w;
#pragma unroll
        for (int o = 16; o > 0; o >>= 1) d0 += __shfl_xor_sync(0xffffffffu, d0, o);
        d0 *= scale;
        mloc = fmaxf(mloc, d0);
        if (lane == 0) s_sc[pos] = d0;
    }

    if (lane == 0) s_red[wid] = mloc;
    __syncthreads();
    float M = -1e30f;
#pragma unroll
    for (int w = 0; w < 8; w++) M = fmaxf(M, s_red[w]);

    float lsum = 0.f;
    for (int i = tid; i <= pos; i += 256) {
        float p = __expf(s_sc[i] - M);
        s_sc[i] = p;
        lsum += p;
    }
#pragma unroll
    for (int o = 16; o > 0; o >>= 1) lsum += __shfl_xor_sync(0xffffffffu, lsum, o);
    __syncthreads();
    if (lane == 0) s_red[wid] = lsum;
    __syncthreads();
    float L = 0.f;
#pragma unroll
    for (int w = 0; w < 8; w++) L += s_red[w];
    const float invL = 1.f / L;

    float4 a4 = make_float4(0.f, 0.f, 0.f, 0.f);
    s = wid;
    for (; s + 24 < pos; s += 32) {
        float4 v[4];
        float  pr[4];
#pragma unroll
        for (int u = 0; u < 4; u++) {
            int su = s + u * 8;
            int a  = ((s_blk[su >> 6] * BS_ + (su & 63)) * H_ + h) * D_;
            v[u]  = *(const float4*)&vcache[a + lane * 4];
            pr[u] = s_sc[su];
        }
#pragma unroll
        for (int u = 0; u < 4; u++) {
            a4.x += pr[u] * v[u].x;
            a4.y += pr[u] * v[u].y;
            a4.z += pr[u] * v[u].z;
            a4.w += pr[u] * v[u].w;
        }
    }
    for (; s < pos; s += 8) {
        int a = ((s_blk[s >> 6] * BS_ + (s & 63)) * H_ + h) * D_;
        float4 v = *(const float4*)&vcache[a + lane * 4];
        float  p = s_sc[s];
        a4.x += p * v.x; a4.y += p * v.y; a4.z += p * v.z; a4.w += p * v.w;
    }
    if ((pos & 7) == wid) {
        const float* vp = &g_qkv[b * TH_ + 2 * HID_ + h * D_];
        float4 v = *(const float4*)&vp[lane * 4];
        float  p = s_sc[pos];
        a4.x += p * v.x; a4.y += p * v.y; a4.z += p * v.z; a4.w += p * v.w;
    }

    *(float4*)&s_acc[wid][lane * 4] = a4;
    __syncthreads();
    if (tid < 128) {
        float val = 0.f;
#pragma unroll
        for (int w = 0; w < 8; w++) val += s_acc[w][tid];
        val *= invL;
        __nv_bfloat16 hi = __float2bfloat16(val);
        g_ahi[b * HID_ + h * D_ + tid] = hi;
        g_alo[b * HID_ + h * D_ + tid] = __float2bfloat16(val - __bfloat162float(hi));
    }
}

// ---------------------------------------------------------------------------
// Kernel 4: oproj via split-bf16 WMMA. out = attn @ Wo^T.
// grid (32 i-tiles, KSPLITO=4) = 128 blocks; k-chunk 1024 in 32 phases.
// B tile = Wo^T staged (Wo rows are k-contiguous -> transpose into smem).
// ---------------------------------------------------------------------------
__global__ __launch_bounds__(256) void oproj_wmma_kernel(const float* __restrict__ Wo) {
    __shared__ __nv_bfloat16 s_whi[32][136];
    __shared__ __nv_bfloat16 s_wlo[32][136];
    __shared__ __nv_bfloat16 s_ahi[32][40];
    __shared__ __nv_bfloat16 s_alo[32][40];
    const int tid = threadIdx.x;
    const int wid = tid >> 5;
    const int i0  = blockIdx.x * 128;
    const int k0  = blockIdx.y * (HID_ / KSPLITO);   // 1024

    wmma::fragment<wmma::accumulator, 16, 16, 16, float> acc0, acc1;
    wmma::fill_fragment(acc0, 0.f);
    wmma::fill_fragment(acc1, 0.f);

    // W prefetch: per phase 128 i x 32 k = 1024 float4; thread: n = idx>>3, kq = idx&7
    float4 wreg[4];
#pragma unroll
    for (int t = 0; t < 4; t++) {
        int idx = tid + t * 256;
        wreg[t] = *(const float4*)&Wo[(size_t)(i0 + (idx >> 3)) * HID_ + k0 + (idx & 7) * 4];
    }

    const __nv_bfloat16* asrc = (tid < 128) ? g_ahi : g_alo;
    __nv_bfloat16* adst = (tid < 128) ? &s_ahi[0][0] : &s_alo[0][0];
    const int ai   = tid & 127;
    const int arow = ai >> 2;
    const int acol = (ai & 3) * 8;

    for (int ph = 0; ph < 32; ph++) {
        uint4 areg = *(const uint4*)&asrc[arow * HID_ + k0 + ph * 32 + acol];
        __syncthreads();
        // stage W^T: s_whi[k][n] = bf16(Wo[(i0+n)*HID + k]); w4 covers 4 consecutive k
#pragma unroll
        for (int t = 0; t < 4; t++) {
            int idx = tid + t * 256;
            int n   = idx >> 3;
            int kq  = (idx & 7) * 4;
            float4 w4 = wreg[t];
            __nv_bfloat16 h0 = __float2bfloat16(w4.x);
            __nv_bfloat16 h1 = __float2bfloat16(w4.y);
            __nv_bfloat16 h2 = __float2bfloat16(w4.z);
            __nv_bfloat16 h3 = __float2bfloat16(w4.w);
            s_whi[kq + 0][n] = h0;
            s_whi[kq + 1][n] = h1;
            s_whi[kq + 2][n] = h2;
            s_whi[kq + 3][n] = h3;
            s_wlo[kq + 0][n] = __float2bfloat16(w4.x - __bfloat162float(h0));
            s_wlo[kq + 1][n] = __float2bfloat16(w4.y - __bfloat162float(h1));
            s_wlo[kq + 2][n] = __float2bfloat16(w4.z - __bfloat162float(h2));
            s_wlo[kq + 3][n] = __float2bfloat16(w4.w - __bfloat162float(h3));
        }
        *(uint4*)&adst[arow * 40 + acol] = areg;
        __syncthreads();

        if (ph + 1 < 32) {
#pragma unroll
            for (int t = 0; t < 4; t++) {
                int idx = tid + t * 256;
                wreg[t] = *(const float4*)&Wo[(size_t)(i0 + (idx >> 3)) * HID_ + k0 + (ph + 1) * 32 + (idx & 7) * 4];
            }
        }

#pragma unroll
        for (int kt = 0; kt < 2; kt++) {
            wmma::fragment<wmma::matrix_a, 16, 16, 16, __nv_bfloat16, wmma::row_major> ahi0, alo0, ahi1, alo1;
            wmma::fragment<wmma::matrix_b, 16, 16, 16, __nv_bfloat16, wmma::row_major> bhi, blo;
            wmma::load_matrix_sync(ahi0, &s_ahi[0][kt * 16], 40);
            wmma::load_matrix_sync(ahi1, &s_ahi[16][kt * 16], 40);
            wmma::load_matrix_sync(alo0, &s_alo[0][kt * 16], 40);
            wmma::load_matrix_sync(alo1, &s_alo[16][kt * 16], 40);
            wmma::load_matrix_sync(bhi, &s_whi[kt * 16][wid * 16], 136);
            wmma::load_matrix_sync(blo, &s_wlo[kt * 16][wid * 16], 136);
            wmma::mma_sync(acc0, ahi0, bhi, acc0);
            wmma::mma_sync(acc1, ahi1, bhi, acc1);
            wmma::mma_sync(acc0, alo0, bhi, acc0);
            wmma::mma_sync(acc1, alo1, bhi, acc1);
            wmma::mma_sync(acc0, ahi0, blo, acc0);
            wmma::mma_sync(acc1, ahi1, blo, acc1);
        }
    }

    float* outp = &g_part[blockIdx.y][0];   // partial [b][i], ld HID_
    wmma::store_matrix_sync(&outp[i0 + wid * 16], acc0, HID_, wmma::mem_row_major);
    wmma::store_matrix_sync(&outp[(size_t)16 * HID_ + i0 + wid * 16], acc1, HID_, wmma::mem_row_major);
}

// Reduce KSPLITO oproj partials -> out. grid 128 x 256.
__global__ __launch_bounds__(256) void oproj_reduce_kernel(float* __restrict__ out) {
    int i = (blockIdx.x * 256 + threadIdx.x) * 4;
    float4 r = *(const float4*)&g_part[0][i];
#pragma unroll
    for (int p = 1; p < KSPLITO; p++) {
        float4 a = *(const float4*)&g_part[p][i];
        r.x += a.x; r.y += a.y; r.z += a.z; r.w += a.w;
    }
    *(float4*)&out[i] = r;
}

// ---------------------------------------------------------------------------
extern "C" void kernel_launch(void* const* d_in, const int* in_sizes, int n_in,
                              void* d_out, int out_size) {
    const float* hidden = (const float*)d_in[0];
    const float* W      = (const float*)d_in[1];
    const float* Wo     = (const float*)d_in[2];
    const float* kcache = (const float*)d_in[3];
    const float* vcache = (const float*)d_in[4];
    const int*   hist   = (const int*)d_in[5];
    const int*   boff   = (const int*)d_in[6];
    float*       out    = (float*)d_out;

    hsplit_kernel<<<B_ * HID_ / 256, 256>>>(hidden, hist);
    qkv_wmma_kernel<<<dim3(TH_ / 128, KSPLIT), 256>>>(W);
    qkv_reduce_rope<<<256, 256>>>(0);
    attn_kernel<<<B_ * H_, 256>>>(kcache, vcache, hist, boff);
    oproj_wmma_kernel<<<dim3(HID_ / 128, KSPLITO), 256>>>(Wo);
    oproj_reduce_kernel<<<B_ * HID_ / 1024, 256>>>(out);
}

// round 14
// speedup vs baseline: 1.6106x; 1.1181x over previous
#include <cuda_runtime.h>
#include <cuda_bf16.h>
#include <mma.h>
#include <math.h>

using namespace nvcuda;

#define B_    32
#define H_    32
#define D_    128
#define HID_  4096
#define TH_   12288      // 3*HID
#define BS_   64
#define NBLK_ 16
#define KSPLIT 8
#define KSPLITO 4

__device__ float g_part[KSPLIT][B_ * TH_];  // qkv partials (reused by oproj)
__device__ float g_qkv[B_ * TH_];           // [b][j]; j<4096 q, ..8191 k, .. v
__device__ float g_cs[B_][64][2];           // rope cos/sin table
__device__ __nv_bfloat16 g_hhi[B_ * HID_];  // hidden split hi
__device__ __nv_bfloat16 g_hlo[B_ * HID_];  // hidden split lo
__device__ __nv_bfloat16 g_ahi[B_ * HID_];  // attn split hi
__device__ __nv_bfloat16 g_alo[B_ * HID_];  // attn split lo

// ---------------------------------------------------------------------------
// Kernel 0: split hidden into bf16 hi/lo; blocks 0-31 also fill rope table.
// ---------------------------------------------------------------------------
__global__ __launch_bounds__(256) void hsplit_kernel(const float* __restrict__ hidden,
                                                     const int* __restrict__ hist) {
    int i = blockIdx.x * 256 + threadIdx.x;
    float x = hidden[i];
    __nv_bfloat16 hi = __float2bfloat16(x);
    g_hhi[i] = hi;
    g_hlo[i] = __float2bfloat16(x - __bfloat162float(hi));

    if (blockIdx.x < 32 && threadIdx.x < 64) {
        const int b = blockIdx.x;
        const int f = threadIdx.x;
        double invd = exp(-(double)f / 64.0 * 9.210340371976184);  // ln(10000)
        double angd = fmod((double)hist[b] * invd, 6.283185307179586476925286766559);
        g_cs[b][f][0] = cosf((float)angd);
        g_cs[b][f][1] = sinf((float)angd);
    }
}

// ---------------------------------------------------------------------------
// Kernel 1: qkv split-bf16 WMMA, DOUBLE-BUFFERED (one sync per phase).
// grid (96 j-tiles, KSPLIT=8), block 256 = 8 warps.
// ---------------------------------------------------------------------------
__global__ __launch_bounds__(256) void qkv_wmma_kernel(const float* __restrict__ W) {
    __shared__ __nv_bfloat16 s_whi[2][32][136];
    __shared__ __nv_bfloat16 s_wlo[2][32][136];
    __shared__ __nv_bfloat16 s_ahi[2][32][40];
    __shared__ __nv_bfloat16 s_alo[2][32][40];
    const int tid = threadIdx.x;
    const int wid = tid >> 5;
    const int j0  = blockIdx.x * 128;
    const int k0  = blockIdx.y * (HID_ / KSPLIT);   // 512

    wmma::fragment<wmma::accumulator, 16, 16, 16, float> acc0, acc1;
    wmma::fill_fragment(acc0, 0.f);
    wmma::fill_fragment(acc1, 0.f);

    const float* wbase = W + j0;
    const int widx_r = (tid + 0) >> 5;   // helper decompositions done inline below

    const __nv_bfloat16* asrc = (tid < 128) ? g_hhi : g_hlo;
    const int ai   = tid & 127;
    const int arow = ai >> 2;
    const int acol = (ai & 3) * 8;

    // ---- prologue: stage phase 0 into buf 0; prefetch W(phase 1) ----
    float4 wreg[4];
#pragma unroll
    for (int t = 0; t < 4; t++) {
        int idx = tid + t * 256;
        wreg[t] = *(const float4*)&wbase[(size_t)(k0 + (idx >> 5)) * TH_ + (idx & 31) * 4];
    }
    {
        uint4 areg = *(const uint4*)&asrc[arow * HID_ + k0 + acol];
#pragma unroll
        for (int t = 0; t < 4; t++) {
            int idx = tid + t * 256;
            int row = idx >> 5;
            int col = (idx & 31) * 4;
            float4 w4 = wreg[t];
            __nv_bfloat16 h0 = __float2bfloat16(w4.x);
            __nv_bfloat16 h1 = __float2bfloat16(w4.y);
            __nv_bfloat16 h2 = __float2bfloat16(w4.z);
            __nv_bfloat16 h3 = __float2bfloat16(w4.w);
            s_whi[0][row][col + 0] = h0;
            s_whi[0][row][col + 1] = h1;
            s_whi[0][row][col + 2] = h2;
            s_whi[0][row][col + 3] = h3;
            s_wlo[0][row][col + 0] = __float2bfloat16(w4.x - __bfloat162float(h0));
            s_wlo[0][row][col + 1] = __float2bfloat16(w4.y - __bfloat162float(h1));
            s_wlo[0][row][col + 2] = __float2bfloat16(w4.z - __bfloat162float(h2));
            s_wlo[0][row][col + 3] = __float2bfloat16(w4.w - __bfloat162float(h3));
        }
        if (tid < 128) *(uint4*)&s_ahi[0][arow][acol] = areg;
        else           *(uint4*)&s_alo[0][arow][acol] = areg;
    }
#pragma unroll
    for (int t = 0; t < 4; t++) {
        int idx = tid + t * 256;
        wreg[t] = *(const float4*)&wbase[(size_t)(k0 + 32 + (idx >> 5)) * TH_ + (idx & 31) * 4];
    }
    __syncthreads();

    for (int ph = 0; ph < 16; ph++) {
        const int buf = ph & 1;
        const int nbf = buf ^ 1;
        if (ph < 15) {
            uint4 areg = *(const uint4*)&asrc[arow * HID_ + k0 + (ph + 1) * 32 + acol];
            // stage next phase into nbf (overlaps other warps' MMAs)
#pragma unroll
            for (int t = 0; t < 4; t++) {
                int idx = tid + t * 256;
                int row = idx >> 5;
                int col = (idx & 31) * 4;
                float4 w4 = wreg[t];
                __nv_bfloat16 h0 = __float2bfloat16(w4.x);
                __nv_bfloat16 h1 = __float2bfloat16(w4.y);
                __nv_bfloat16 h2 = __float2bfloat16(w4.z);
                __nv_bfloat16 h3 = __float2bfloat16(w4.w);
                s_whi[nbf][row][col + 0] = h0;
                s_whi[nbf][row][col + 1] = h1;
                s_whi[nbf][row][col + 2] = h2;
                s_whi[nbf][row][col + 3] = h3;
                s_wlo[nbf][row][col + 0] = __float2bfloat16(w4.x - __bfloat162float(h0));
                s_wlo[nbf][row][col + 1] = __float2bfloat16(w4.y - __bfloat162float(h1));
                s_wlo[nbf][row][col + 2] = __float2bfloat16(w4.z - __bfloat162float(h2));
                s_wlo[nbf][row][col + 3] = __float2bfloat16(w4.w - __bfloat162float(h3));
            }
            if (tid < 128) *(uint4*)&s_ahi[nbf][arow][acol] = areg;
            else           *(uint4*)&s_alo[nbf][arow][acol] = areg;
            if (ph < 14) {
#pragma unroll
                for (int t = 0; t < 4; t++) {
                    int idx = tid + t * 256;
                    wreg[t] = *(const float4*)&wbase[(size_t)(k0 + (ph + 2) * 32 + (idx >> 5)) * TH_ + (idx & 31) * 4];
                }
            }
        }

#pragma unroll
        for (int kt = 0; kt < 2; kt++) {
            wmma::fragment<wmma::matrix_a, 16, 16, 16, __nv_bfloat16, wmma::row_major> ahi0, alo0, ahi1, alo1;
            wmma::fragment<wmma::matrix_b, 16, 16, 16, __nv_bfloat16, wmma::row_major> bhi, blo;
            wmma::load_matrix_sync(ahi0, &s_ahi[buf][0][kt * 16], 40);
            wmma::load_matrix_sync(ahi1, &s_ahi[buf][16][kt * 16], 40);
            wmma::load_matrix_sync(alo0, &s_alo[buf][0][kt * 16], 40);
            wmma::load_matrix_sync(alo1, &s_alo[buf][16][kt * 16], 40);
            wmma::load_matrix_sync(bhi, &s_whi[buf][kt * 16][wid * 16], 136);
            wmma::load_matrix_sync(blo, &s_wlo[buf][kt * 16][wid * 16], 136);
            wmma::mma_sync(acc0, ahi0, bhi, acc0);
            wmma::mma_sync(acc1, ahi1, bhi, acc1);
            wmma::mma_sync(acc0, alo0, bhi, acc0);
            wmma::mma_sync(acc1, alo1, bhi, acc1);
            wmma::mma_sync(acc0, ahi0, blo, acc0);
            wmma::mma_sync(acc1, ahi1, blo, acc1);
        }
        __syncthreads();
    }

    float* outp = &g_part[blockIdx.y][0];
    wmma::store_matrix_sync(&outp[j0 + wid * 16], acc0, TH_, wmma::mem_row_major);
    wmma::store_matrix_sync(&outp[(size_t)16 * TH_ + j0 + wid * 16], acc1, TH_, wmma::mem_row_major);
    (void)widx_r;
}

// ---------------------------------------------------------------------------
// Kernel 2: reduce KSPLIT partials + apply RoPE inline. grid 256 x 256.
// ---------------------------------------------------------------------------
__global__ __launch_bounds__(256) void qkv_reduce_rope(int dummy) {
    const int t = blockIdx.x * 256 + threadIdx.x;
    if (t < 32768) {
        const int b    = t >> 10;
        const int rem  = t & 1023;
        const int part = rem >> 9;
        const int rem2 = rem & 511;
        const int h    = rem2 >> 4;
        const int dq   = rem2 & 15;
        const int d0   = dq * 4;
        const int idx_lo = b * TH_ + part * HID_ + h * D_ + d0;
        const int idx_hi = idx_lo + 64;

        float4 rl = *(const float4*)&g_part[0][idx_lo];
        float4 rh = *(const float4*)&g_part[0][idx_hi];
#pragma unroll
        for (int p = 1; p < KSPLIT; p++) {
            float4 a = *(const float4*)&g_part[p][idx_lo];
            float4 c = *(const float4*)&g_part[p][idx_hi];
            rl.x += a.x; rl.y += a.y; rl.z += a.z; rl.w += a.w;
            rh.x += c.x; rh.y += c.y; rh.z += c.z; rh.w += c.w;
        }
        float4 cs0 = *(const float4*)&g_cs[b][d0][0];
        float4 cs1 = *(const float4*)&g_cs[b][d0 + 2][0];
        float4 ol, oh;
        ol.x = rl.x * cs0.x - rh.x * cs0.y;  oh.x = rh.x * cs0.x + rl.x * cs0.y;
        ol.y = rl.y * cs0.z - rh.y * cs0.w;  oh.y = rh.y * cs0.z + rl.y * cs0.w;
        ol.z = rl.z * cs1.x - rh.z * cs1.y;  oh.z = rh.z * cs1.x + rl.z * cs1.y;
        ol.w = rl.w * cs1.z - rh.w * cs1.w;  oh.w = rh.w * cs1.z + rl.w * cs1.w;
        *(float4*)&g_qkv[idx_lo] = ol;
        *(float4*)&g_qkv[idx_hi] = oh;
    } else {
        const int t2  = t - 32768;
        const int b   = t2 >> 10;
        const int off = (t2 & 1023) * 4;
        const int idx = b * TH_ + 2 * HID_ + off;
        float4 r = *(const float4*)&g_part[0][idx];
#pragma unroll
        for (int p = 1; p < KSPLIT; p++) {
            float4 a = *(const float4*)&g_part[p][idx];
            r.x += a.x; r.y += a.y; r.z += a.z; r.w += a.w;
        }
        *(float4*)&g_qkv[idx] = r;
    }
}

// ---------------------------------------------------------------------------
// Kernel 3: attention, two-phase, unroll 8. Epilogue writes bf16 hi/lo split.
// ---------------------------------------------------------------------------
__global__ __launch_bounds__(256) void attn_kernel(const float* __restrict__ kcache,
                                                   const float* __restrict__ vcache,
                                                   const int* __restrict__ hist,
                                                   const int* __restrict__ boff) {
    const int b = blockIdx.x >> 5;
    const int h = blockIdx.x & 31;
    const int tid  = threadIdx.x;
    const int lane = tid & 31;
    const int wid  = tid >> 5;

    __shared__ int   s_blk[NBLK_];
    __shared__ float s_sc[1024];
    __shared__ float s_red[8];
    __shared__ float s_acc[8][128];

    if (tid < NBLK_) s_blk[tid] = boff[b * NBLK_ + tid];
    __syncthreads();

    const int pos = hist[b];
    const float scale = 0.08838834764831845f;  // 1/sqrt(128)
    const float4 q4 = *(const float4*)&g_qkv[b * TH_ + h * D_ + lane * 4];

    // ---- phase 1: scores, 8-deep MLP ----
    float mloc = -1e30f;
    int s = wid;
    for (; s + 56 < pos; s += 64) {
        float4 k[8];
        int    sp[8];
#pragma unroll
        for (int u = 0; u < 8; u++) {
            sp[u] = s + u * 8;
            int a = ((s_blk[sp[u] >> 6] * BS_ + (sp[u] & 63)) * H_ + h) * D_;
            k[u] = *(const float4*)&kcache[a + lane * 4];
        }
        float dt[8];
#pragma unroll
        for (int u = 0; u < 8; u++)
            dt[u] = q4.x * k[u].x + q4.y * k[u].y + q4.z * k[u].z + q4.w * k[u].w;
#pragma unroll
        for (int o = 16; o > 0; o >>= 1)
#pragma unroll
            for (int u = 0; u < 8; u++)
                dt[u] += __shfl_xor_sync(0xffffffffu, dt[u], o);
#pragma unroll
        for (int u = 0; u < 8; u++) {
            dt[u] *= scale;
            mloc = fmaxf(mloc, dt[u]);
            if (lane == 0) s_sc[sp[u]] = dt[u];
        }
    }
    for (; s < pos; s += 8) {
        int a0 = ((s_blk[s >> 6] * BS_ + (s & 63)) * H_ + h) * D_;
        float4 k0 = *(const float4*)&kcache[a0 + lane * 4];
        float d0 = q4.x * k0.x + q4.y * k0.y + q4.z * k0.z + q4.w * k0.w;
#pragma unroll
        for (int o = 16; o > 0; o >>= 1) d0 += __shfl_xor_sync(0xffffffffu, d0, o);
        d0 *= scale;
        mloc = fmaxf(mloc, d0);
        if (lane == 0) s_sc[s] = d0;
    }
    if ((pos & 7) == wid) {      // fresh k at s == pos (ref writes cache first)
        const float* kp = &g_qkv[b * TH_ + HID_ + h * D_];
        float4 k0 = *(const float4*)&kp[lane * 4];
        float d0 = q4.x * k0.x + q4.y * k0.y + q4.z * k0.z + q4.w * k0.w;
#pragma unroll
        for (int o = 16; o > 0; o >>= 1) d0 += __shfl_xor_sync(0xffffffffu, d0, o);
        d0 *= scale;
        mloc = fmaxf(mloc, d0);
        if (lane == 0) s_sc[pos] = d0;
    }

    if (lane == 0) s_red[wid] = mloc;
    __syncthreads();
    float M = -1e30f;
#pragma unroll
    for (int w = 0; w < 8; w++) M = fmaxf(M, s_red[w]);

    float lsum = 0.f;
    for (int i = tid; i <= pos; i += 256) {
        float p = __expf(s_sc[i] - M);
        s_sc[i] = p;
        lsum += p;
    }
#pragma unroll
    for (int o = 16; o > 0; o >>= 1) lsum += __shfl_xor_sync(0xffffffffu, lsum, o);
    __syncthreads();
    if (lane == 0) s_red[wid] = lsum;
    __syncthreads();
    float L = 0.f;
#pragma unroll
    for (int w = 0; w < 8; w++) L += s_red[w];
    const float invL = 1.f / L;

    // ---- phase 2: V stream, 8-deep MLP ----
    float4 a4 = make_float4(0.f, 0.f, 0.f, 0.f);
    s = wid;
    for (; s + 56 < pos; s += 64) {
        float4 v[8];
        float  pr[8];
#pragma unroll
        for (int u = 0; u < 8; u++) {
            int su = s + u * 8;
            int a  = ((s_blk[su >> 6] * BS_ + (su & 63)) * H_ + h) * D_;
            v[u]  = *(const float4*)&vcache[a + lane * 4];
            pr[u] = s_sc[su];
        }
#pragma unroll
        for (int u = 0; u < 8; u++) {
            a4.x += pr[u] * v[u].x;
            a4.y += pr[u] * v[u].y;
            a4.z += pr[u] * v[u].z;
            a4.w += pr[u] * v[u].w;
        }
    }
    for (; s < pos; s += 8) {
        int a = ((s_blk[s >> 6] * BS_ + (s & 63)) * H_ + h) * D_;
        float4 v = *(const float4*)&vcache[a + lane * 4];
        float  p = s_sc[s];
        a4.x += p * v.x; a4.y += p * v.y; a4.z += p * v.z; a4.w += p * v.w;
    }
    if ((pos & 7) == wid) {
        const float* vp = &g_qkv[b * TH_ + 2 * HID_ + h * D_];
        float4 v = *(const float4*)&vp[lane * 4];
        float  p = s_sc[pos];
        a4.x += p * v.x; a4.y += p * v.y; a4.z += p * v.z; a4.w += p * v.w;
    }

    *(float4*)&s_acc[wid][lane * 4] = a4;
    __syncthreads();
    if (tid < 128) {
        float val = 0.f;
#pragma unroll
        for (int w = 0; w < 8; w++) val += s_acc[w][tid];
        val *= invL;
        __nv_bfloat16 hi = __float2bfloat16(val);
        g_ahi[b * HID_ + h * D_ + tid] = hi;
        g_alo[b * HID_ + h * D_ + tid] = __float2bfloat16(val - __bfloat162float(hi));
    }
}

// ---------------------------------------------------------------------------
// Kernel 4: oproj split-bf16 WMMA, DOUBLE-BUFFERED. grid (32, KSPLITO=4).
// ---------------------------------------------------------------------------
__global__ __launch_bounds__(256) void oproj_wmma_kernel(const float* __restrict__ Wo) {
    __shared__ __nv_bfloat16 s_whi[2][32][136];
    __shared__ __nv_bfloat16 s_wlo[2][32][136];
    __shared__ __nv_bfloat16 s_ahi[2][32][40];
    __shared__ __nv_bfloat16 s_alo[2][32][40];
    const int tid = threadIdx.x;
    const int wid = tid >> 5;
    const int i0  = blockIdx.x * 128;
    const int k0  = blockIdx.y * (HID_ / KSPLITO);   // 1024

    wmma::fragment<wmma::accumulator, 16, 16, 16, float> acc0, acc1;
    wmma::fill_fragment(acc0, 0.f);
    wmma::fill_fragment(acc1, 0.f);

    const __nv_bfloat16* asrc = (tid < 128) ? g_ahi : g_alo;
    const int ai   = tid & 127;
    const int arow = ai >> 2;
    const int acol = (ai & 3) * 8;

    float4 wreg[4];
#pragma unroll
    for (int t = 0; t < 4; t++) {
        int idx = tid + t * 256;
        wreg[t] = *(const float4*)&Wo[(size_t)(i0 + (idx >> 3)) * HID_ + k0 + (idx & 7) * 4];
    }
    {
        uint4 areg = *(const uint4*)&asrc[arow * HID_ + k0 + acol];
#pragma unroll
        for (int t = 0; t < 4; t++) {
            int idx = tid + t * 256;
            int n   = idx >> 3;
            int kq  = (idx & 7) * 4;
            float4 w4 = wreg[t];
            __nv_bfloat16 h0 = __float2bfloat16(w4.x);
            __nv_bfloat16 h1 = __float2bfloat16(w4.y);
            __nv_bfloat16 h2 = __float2bfloat16(w4.z);
            __nv_bfloat16 h3 = __float2bfloat16(w4.w);
            s_whi[0][kq + 0][n] = h0;
            s_whi[0][kq + 1][n] = h1;
            s_whi[0][kq + 2][n] = h2;
            s_whi[0][kq + 3][n] = h3;
            s_wlo[0][kq + 0][n] = __float2bfloat16(w4.x - __bfloat162float(h0));
            s_wlo[0][kq + 1][n] = __float2bfloat16(w4.y - __bfloat162float(h1));
            s_wlo[0][kq + 2][n] = __float2bfloat16(w4.z - __bfloat162float(h2));
            s_wlo[0][kq + 3][n] = __float2bfloat16(w4.w - __bfloat162float(h3));
        }
        if (tid < 128) *(uint4*)&s_ahi[0][arow][acol] = areg;
        else           *(uint4*)&s_alo[0][arow][acol] = areg;
    }
#pragma unroll
    for (int t = 0; t < 4; t++) {
        int idx = tid + t * 256;
        wreg[t] = *(const float4*)&Wo[(size_t)(i0 + (idx >> 3)) * HID_ + k0 + 32 + (idx & 7) * 4];
    }
    __syncthreads();

    for (int ph = 0; ph < 32; ph++) {
        const int buf = ph & 1;
        const int nbf = buf ^ 1;
        if (ph < 31) {
            uint4 areg = *(const uint4*)&asrc[arow * HID_ + k0 + (ph + 1) * 32 + acol];
#pragma unroll
            for (int t = 0; t < 4; t++) {
                int idx = tid + t * 256;
                int n   = idx >> 3;
                int kq  = (idx & 7) * 4;
                float4 w4 = wreg[t];
                __nv_bfloat16 h0 = __float2bfloat16(w4.x);
                __nv_bfloat16 h1 = __float2bfloat16(w4.y);
                __nv_bfloat16 h2 = __float2bfloat16(w4.z);
                __nv_bfloat16 h3 = __float2bfloat16(w4.w);
                s_whi[nbf][kq + 0][n] = h0;
                s_whi[nbf][kq + 1][n] = h1;
                s_whi[nbf][kq + 2][n] = h2;
                s_whi[nbf][kq + 3][n] = h3;
                s_wlo[nbf][kq + 0][n] = __float2bfloat16(w4.x - __bfloat162float(h0));
                s_wlo[nbf][kq + 1][n] = __float2bfloat16(w4.y - __bfloat162float(h1));
                s_wlo[nbf][kq + 2][n] = __float2bfloat16(w4.z - __bfloat162float(h2));
                s_wlo[nbf][kq + 3][n] = __float2bfloat16(w4.w - __bfloat162float(h3));
            }
            if (tid < 128) *(uint4*)&s_ahi[nbf][arow][acol] = areg;
            else           *(uint4*)&s_alo[nbf][arow][acol] = areg;
            if (ph < 30) {
#pragma unroll
                for (int t = 0; t < 4; t++) {
                    int idx = tid + t * 256;
                    wreg[t] = *(const float4*)&Wo[(size_t)(i0 + (idx >> 3)) * HID_ + k0 + (ph + 2) * 32 + (idx & 7) * 4];
                }
            }
        }

#pragma unroll
        for (int kt = 0; kt < 2; kt++) {
            wmma::fragment<wmma::matrix_a, 16, 16, 16, __nv_bfloat16, wmma::row_major> ahi0, alo0, ahi1, alo1;
            wmma::fragment<wmma::matrix_b, 16, 16, 16, __nv_bfloat16, wmma::row_major> bhi, blo;
            wmma::load_matrix_sync(ahi0, &s_ahi[buf][0][kt * 16], 40);
            wmma::load_matrix_sync(ahi1, &s_ahi[buf][16][kt * 16], 40);
            wmma::load_matrix_sync(alo0, &s_alo[buf][0][kt * 16], 40);
            wmma::load_matrix_sync(alo1, &s_alo[buf][16][kt * 16], 40);
            wmma::load_matrix_sync(bhi, &s_whi[buf][kt * 16][wid * 16], 136);
            wmma::load_matrix_sync(blo, &s_wlo[buf][kt * 16][wid * 16], 136);
            wmma::mma_sync(acc0, ahi0, bhi, acc0);
            wmma::mma_sync(acc1, ahi1, bhi, acc1);
            wmma::mma_sync(acc0, alo0, bhi, acc0);
            wmma::mma_sync(acc1, alo1, bhi, acc1);
            wmma::mma_sync(acc0, ahi0, blo, acc0);
            wmma::mma_sync(acc1, ahi1, blo, acc1);
        }
        __syncthreads();
    }

    float* outp = &g_part[blockIdx.y][0];
    wmma::store_matrix_sync(&outp[i0 + wid * 16], acc0, HID_, wmma::mem_row_major);
    wmma::store_matrix_sync(&outp[(size_t)16 * HID_ + i0 + wid * 16], acc1, HID_, wmma::mem_row_major);
}

// Reduce KSPLITO oproj partials -> out.
__global__ __launch_bounds__(256) void oproj_reduce_kernel(float* __restrict__ out) {
    int i = (blockIdx.x * 256 + threadIdx.x) * 4;
    float4 r = *(const float4*)&g_part[0][i];
#pragma unroll
    for (int p = 1; p < KSPLITO; p++) {
        float4 a = *(const float4*)&g_part[p][i];
        r.x += a.x; r.y += a.y; r.z += a.z; r.w += a.w;
    }
    *(float4*)&out[i] = r;
}

// ---------------------------------------------------------------------------
extern "C" void kernel_launch(void* const* d_in, const int* in_sizes, int n_in,
                              void* d_out, int out_size) {
    const float* hidden = (const float*)d_in[0];
    const float* W      = (const float*)d_in[1];
    const float* Wo     = (const float*)d_in[2];
    const float* kcache = (const float*)d_in[3];
    const float* vcache = (const float*)d_in[4];
    const int*   hist   = (const int*)d_in[5];
    const int*   boff   = (const int*)d_in[6];
    float*       out    = (float*)d_out;

    hsplit_kernel<<<B_ * HID_ / 256, 256>>>(hidden, hist);
    qkv_wmma_kernel<<<dim3(TH_ / 128, KSPLIT), 256>>>(W);
    qkv_reduce_rope<<<256, 256>>>(0);
    attn_kernel<<<B_ * H_, 256>>>(kcache, vcache, hist, boff);
    oproj_wmma_kernel<<<dim3(HID_ / 128, KSPLITO), 256>>>(Wo);
    oproj_reduce_kernel<<<B_ * HID_ / 1024, 256>>>(out);
}

// round 15
// speedup vs baseline: 1.7151x; 1.0649x over previous
#include <cuda_runtime.h>
#include <cuda_bf16.h>
#include <mma.h>
#include <math.h>

using namespace nvcuda;

#define B_    32
#define H_    32
#define D_    128
#define HID_  4096
#define TH_   12288      // 3*HID
#define BS_   64
#define NBLK_ 16
#define KSPLIT 8
#define KSPLITO 4

__device__ float g_part[KSPLIT][B_ * TH_];  // qkv partials (reused by oproj)
__device__ float g_qkv[B_ * TH_];           // [b][j]; j<4096 q, ..8191 k, .. v
__device__ float g_cs[B_][64][2];           // rope cos/sin table
__device__ __nv_bfloat16 g_hhi[B_ * HID_];  // hidden split hi
__device__ __nv_bfloat16 g_hlo[B_ * HID_];  // hidden split lo
__device__ __nv_bfloat16 g_ahi[B_ * HID_];  // attn split hi
__device__ __nv_bfloat16 g_alo[B_ * HID_];  // attn split lo

// pack (f0, f1) -> bf16x2 word (f0 in low half), and hi/lo split helpers
__device__ __forceinline__ unsigned bfpack(float f0, float f1) {
    __nv_bfloat162 p = __floats2bfloat162_rn(f0, f1);
    return *(unsigned*)&p;
}
__device__ __forceinline__ float bflow(unsigned w)  { return __uint_as_float(w << 16); }
__device__ __forceinline__ float bfhigh(unsigned w) { return __uint_as_float(w & 0xffff0000u); }

// ---------------------------------------------------------------------------
// Kernel 0: split hidden into bf16 hi/lo; blocks 0-31 also fill rope table.
// ---------------------------------------------------------------------------
__global__ __launch_bounds__(256) void hsplit_kernel(const float* __restrict__ hidden,
                                                     const int* __restrict__ hist) {
    int i = blockIdx.x * 256 + threadIdx.x;
    float x = hidden[i];
    __nv_bfloat16 hi = __float2bfloat16(x);
    g_hhi[i] = hi;
    g_hlo[i] = __float2bfloat16(x - __bfloat162float(hi));

    if (blockIdx.x < 32 && threadIdx.x < 64) {
        const int b = blockIdx.x;
        const int f = threadIdx.x;
        double invd = exp(-(double)f / 64.0 * 9.210340371976184);  // ln(10000)
        double angd = fmod((double)hist[b] * invd, 6.283185307179586476925286766559);
        g_cs[b][f][0] = cosf((float)angd);
        g_cs[b][f][1] = sinf((float)angd);
    }
}

// ---------------------------------------------------------------------------
// Kernel 1: qkv split-bf16 WMMA, double-buffered, PACKED STS.64 staging.
// grid (96 j-tiles, KSPLIT=8), block 256 = 8 warps.
// ---------------------------------------------------------------------------
__global__ __launch_bounds__(256) void qkv_wmma_kernel(const float* __restrict__ W) {
    __shared__ __align__(16) __nv_bfloat16 s_whi[2][32][136];
    __shared__ __align__(16) __nv_bfloat16 s_wlo[2][32][136];
    __shared__ __align__(16) __nv_bfloat16 s_ahi[2][32][40];
    __shared__ __align__(16) __nv_bfloat16 s_alo[2][32][40];
    const int tid = threadIdx.x;
    const int wid = tid >> 5;
    const int j0  = blockIdx.x * 128;
    const int k0  = blockIdx.y * (HID_ / KSPLIT);   // 512

    wmma::fragment<wmma::accumulator, 16, 16, 16, float> acc0, acc1;
    wmma::fill_fragment(acc0, 0.f);
    wmma::fill_fragment(acc1, 0.f);

    const float* wbase = W + j0;
    const __nv_bfloat16* asrc = (tid < 128) ? g_hhi : g_hlo;
    const int ai   = tid & 127;
    const int arow = ai >> 2;
    const int acol = (ai & 3) * 8;

    // staging lambda-equivalent macro: 4 w4 -> packed hi/lo STS.64
#define QSTAGE(BUF)                                                              \
    _Pragma("unroll")                                                            \
    for (int t = 0; t < 4; t++) {                                                \
        int idx = tid + t * 256;                                                 \
        int row = idx >> 5;                                                      \
        int col = (idx & 31) * 4;                                                \
        float4 w4 = wreg[t];                                                     \
        unsigned hA = bfpack(w4.x, w4.y);                                        \
        unsigned hB = bfpack(w4.z, w4.w);                                        \
        unsigned lA = bfpack(w4.x - bflow(hA), w4.y - bfhigh(hA));               \
        unsigned lB = bfpack(w4.z - bflow(hB), w4.w - bfhigh(hB));               \
        *(uint2*)&s_whi[BUF][row][col] = make_uint2(hA, hB);                     \
        *(uint2*)&s_wlo[BUF][row][col] = make_uint2(lA, lB);                     \
    }

    float4 wreg[4];
#pragma unroll
    for (int t = 0; t < 4; t++) {
        int idx = tid + t * 256;
        wreg[t] = *(const float4*)&wbase[(size_t)(k0 + (idx >> 5)) * TH_ + (idx & 31) * 4];
    }
    {
        uint4 areg = *(const uint4*)&asrc[arow * HID_ + k0 + acol];
        QSTAGE(0)
        if (tid < 128) *(uint4*)&s_ahi[0][arow][acol] = areg;
        else           *(uint4*)&s_alo[0][arow][acol] = areg;
    }
#pragma unroll
    for (int t = 0; t < 4; t++) {
        int idx = tid + t * 256;
        wreg[t] = *(const float4*)&wbase[(size_t)(k0 + 32 + (idx >> 5)) * TH_ + (idx & 31) * 4];
    }
    __syncthreads();

    for (int ph = 0; ph < 16; ph++) {
        const int buf = ph & 1;
        const int nbf = buf ^ 1;
        if (ph < 15) {
            uint4 areg = *(const uint4*)&asrc[arow * HID_ + k0 + (ph + 1) * 32 + acol];
            if (nbf) { QSTAGE(1) } else { QSTAGE(0) }
            if (tid < 128) *(uint4*)&s_ahi[nbf][arow][acol] = areg;
            else           *(uint4*)&s_alo[nbf][arow][acol] = areg;
            if (ph < 14) {
#pragma unroll
                for (int t = 0; t < 4; t++) {
                    int idx = tid + t * 256;
                    wreg[t] = *(const float4*)&wbase[(size_t)(k0 + (ph + 2) * 32 + (idx >> 5)) * TH_ + (idx & 31) * 4];
                }
            }
        }

#pragma unroll
        for (int kt = 0; kt < 2; kt++) {
            wmma::fragment<wmma::matrix_a, 16, 16, 16, __nv_bfloat16, wmma::row_major> ahi0, alo0, ahi1, alo1;
            wmma::fragment<wmma::matrix_b, 16, 16, 16, __nv_bfloat16, wmma::row_major> bhi, blo;
            wmma::load_matrix_sync(ahi0, &s_ahi[buf][0][kt * 16], 40);
            wmma::load_matrix_sync(ahi1, &s_ahi[buf][16][kt * 16], 40);
            wmma::load_matrix_sync(alo0, &s_alo[buf][0][kt * 16], 40);
            wmma::load_matrix_sync(alo1, &s_alo[buf][16][kt * 16], 40);
            wmma::load_matrix_sync(bhi, &s_whi[buf][kt * 16][wid * 16], 136);
            wmma::load_matrix_sync(blo, &s_wlo[buf][kt * 16][wid * 16], 136);
            wmma::mma_sync(acc0, ahi0, bhi, acc0);
            wmma::mma_sync(acc1, ahi1, bhi, acc1);
            wmma::mma_sync(acc0, alo0, bhi, acc0);
            wmma::mma_sync(acc1, alo1, bhi, acc1);
            wmma::mma_sync(acc0, ahi0, blo, acc0);
            wmma::mma_sync(acc1, ahi1, blo, acc1);
        }
        __syncthreads();
    }
#undef QSTAGE

    float* outp = &g_part[blockIdx.y][0];
    wmma::store_matrix_sync(&outp[j0 + wid * 16], acc0, TH_, wmma::mem_row_major);
    wmma::store_matrix_sync(&outp[(size_t)16 * TH_ + j0 + wid * 16], acc1, TH_, wmma::mem_row_major);
}

// ---------------------------------------------------------------------------
// Kernel 2: reduce KSPLIT partials + apply RoPE inline. grid 256 x 256.
// ---------------------------------------------------------------------------
__global__ __launch_bounds__(256) void qkv_reduce_rope(int dummy) {
    const int t = blockIdx.x * 256 + threadIdx.x;
    if (t < 32768) {
        const int b    = t >> 10;
        const int rem  = t & 1023;
        const int part = rem >> 9;
        const int rem2 = rem & 511;
        const int h    = rem2 >> 4;
        const int dq   = rem2 & 15;
        const int d0   = dq * 4;
        const int idx_lo = b * TH_ + part * HID_ + h * D_ + d0;
        const int idx_hi = idx_lo + 64;

        float4 rl = *(const float4*)&g_part[0][idx_lo];
        float4 rh = *(const float4*)&g_part[0][idx_hi];
#pragma unroll
        for (int p = 1; p < KSPLIT; p++) {
            float4 a = *(const float4*)&g_part[p][idx_lo];
            float4 c = *(const float4*)&g_part[p][idx_hi];
            rl.x += a.x; rl.y += a.y; rl.z += a.z; rl.w += a.w;
            rh.x += c.x; rh.y += c.y; rh.z += c.z; rh.w += c.w;
        }
        float4 cs0 = *(const float4*)&g_cs[b][d0][0];
        float4 cs1 = *(const float4*)&g_cs[b][d0 + 2][0];
        float4 ol, oh;
        ol.x = rl.x * cs0.x - rh.x * cs0.y;  oh.x = rh.x * cs0.x + rl.x * cs0.y;
        ol.y = rl.y * cs0.z - rh.y * cs0.w;  oh.y = rh.y * cs0.z + rl.y * cs0.w;
        ol.z = rl.z * cs1.x - rh.z * cs1.y;  oh.z = rh.z * cs1.x + rl.z * cs1.y;
        ol.w = rl.w * cs1.z - rh.w * cs1.w;  oh.w = rh.w * cs1.z + rl.w * cs1.w;
        *(float4*)&g_qkv[idx_lo] = ol;
        *(float4*)&g_qkv[idx_hi] = oh;
    } else {
        const int t2  = t - 32768;
        const int b   = t2 >> 10;
        const int off = (t2 & 1023) * 4;
        const int idx = b * TH_ + 2 * HID_ + off;
        float4 r = *(const float4*)&g_part[0][idx];
#pragma unroll
        for (int p = 1; p < KSPLIT; p++) {
            float4 a = *(const float4*)&g_part[p][idx];
            r.x += a.x; r.y += a.y; r.z += a.z; r.w += a.w;
        }
        *(float4*)&g_qkv[idx] = r;
    }
}

// ---------------------------------------------------------------------------
// Kernel 3: attention, two-phase (R14). grid = B*H blocks, 256 threads.
// ---------------------------------------------------------------------------
__global__ __launch_bounds__(256) void attn_kernel(const float* __restrict__ kcache,
                                                   const float* __restrict__ vcache,
                                                   const int* __restrict__ hist,
                                                   const int* __restrict__ boff) {
    const int b = blockIdx.x >> 5;
    const int h = blockIdx.x & 31;
    const int tid  = threadIdx.x;
    const int lane = tid & 31;
    const int wid  = tid >> 5;

    __shared__ int   s_blk[NBLK_];
    __shared__ float s_sc[1024];
    __shared__ float s_red[8];
    __shared__ float s_acc[8][128];

    if (tid < NBLK_) s_blk[tid] = boff[b * NBLK_ + tid];
    __syncthreads();

    const int pos = hist[b];
    const float scale = 0.08838834764831845f;  // 1/sqrt(128)
    const float4 q4 = *(const float4*)&g_qkv[b * TH_ + h * D_ + lane * 4];

    float mloc = -1e30f;
    int s = wid;
    for (; s + 56 < pos; s += 64) {
        float4 k[8];
        int    sp[8];
#pragma unroll
        for (int u = 0; u < 8; u++) {
            sp[u] = s + u * 8;
            int a = ((s_blk[sp[u] >> 6] * BS_ + (sp[u] & 63)) * H_ + h) * D_;
            k[u] = *(const float4*)&kcache[a + lane * 4];
        }
        float dt[8];
#pragma unroll
        for (int u = 0; u < 8; u++)
            dt[u] = q4.x * k[u].x + q4.y * k[u].y + q4.z * k[u].z + q4.w * k[u].w;
#pragma unroll
        for (int o = 16; o > 0; o >>= 1)
#pragma unroll
            for (int u = 0; u < 8; u++)
                dt[u] += __shfl_xor_sync(0xffffffffu, dt[u], o);
#pragma unroll
        for (int u = 0; u < 8; u++) {
            dt[u] *= scale;
            mloc = fmaxf(mloc, dt[u]);
            if (lane == 0) s_sc[sp[u]] = dt[u];
        }
    }
    for (; s < pos; s += 8) {
        int a0 = ((s_blk[s >> 6] * BS_ + (s & 63)) * H_ + h) * D_;
        float4 k0 = *(const float4*)&kcache[a0 + lane * 4];
        float d0 = q4.x * k0.x + q4.y * k0.y + q4.z * k0.z + q4.w * k0.w;
#pragma unroll
        for (int o = 16; o > 0; o >>= 1) d0 += __shfl_xor_sync(0xffffffffu, d0, o);
        d0 *= scale;
        mloc = fmaxf(mloc, d0);
        if (lane == 0) s_sc[s] = d0;
    }
    if ((pos & 7) == wid) {
        const float* kp = &g_qkv[b * TH_ + HID_ + h * D_];
        float4 k0 = *(const float4*)&kp[lane * 4];
        float d0 = q4.x * k0.x + q4.y * k0.y + q4.z * k0.z + q4.w * k0.w;
#pragma unroll
        for (int o = 16; o > 0; o >>= 1) d0 += __shfl_xor_sync(0xffffffffu, d0, o);
        d0 *= scale;
        mloc = fmaxf(mloc, d0);
        if (lane == 0) s_sc[pos] = d0;
    }

    if (lane == 0) s_red[wid] = mloc;
    __syncthreads();
    float M = -1e30f;
#pragma unroll
    for (int w = 0; w < 8; w++) M = fmaxf(M, s_red[w]);

    float lsum = 0.f;
    for (int i = tid; i <= pos; i += 256) {
        float p = __expf(s_sc[i] - M);
        s_sc[i] = p;
        lsum += p;
    }
#pragma unroll
    for (int o = 16; o > 0; o >>= 1) lsum += __shfl_xor_sync(0xffffffffu, lsum, o);
    __syncthreads();
    if (lane == 0) s_red[wid] = lsum;
    __syncthreads();
    float L = 0.f;
#pragma unroll
    for (int w = 0; w < 8; w++) L += s_red[w];
    const float invL = 1.f / L;

    float4 a4 = make_float4(0.f, 0.f, 0.f, 0.f);
    s = wid;
    for (; s + 56 < pos; s += 64) {
        float4 v[8];
        float  pr[8];
#pragma unroll
        for (int u = 0; u < 8; u++) {
            int su = s + u * 8;
            int a  = ((s_blk[su >> 6] * BS_ + (su & 63)) * H_ + h) * D_;
            v[u]  = *(const float4*)&vcache[a + lane * 4];
            pr[u] = s_sc[su];
        }
#pragma unroll
        for (int u = 0; u < 8; u++) {
            a4.x += pr[u] * v[u].x;
            a4.y += pr[u] * v[u].y;
            a4.z += pr[u] * v[u].z;
            a4.w += pr[u] * v[u].w;
        }
    }
    for (; s < pos; s += 8) {
        int a = ((s_blk[s >> 6] * BS_ + (s & 63)) * H_ + h) * D_;
        float4 v = *(const float4*)&vcache[a + lane * 4];
        float  p = s_sc[s];
        a4.x += p * v.x; a4.y += p * v.y; a4.z += p * v.z; a4.w += p * v.w;
    }
    if ((pos & 7) == wid) {
        const float* vp = &g_qkv[b * TH_ + 2 * HID_ + h * D_];
        float4 v = *(const float4*)&vp[lane * 4];
        float  p = s_sc[pos];
        a4.x += p * v.x; a4.y += p * v.y; a4.z += p * v.z; a4.w += p * v.w;
    }

    *(float4*)&s_acc[wid][lane * 4] = a4;
    __syncthreads();
    if (tid < 128) {
        float val = 0.f;
#pragma unroll
        for (int w = 0; w < 8; w++) val += s_acc[w][tid];
        val *= invL;
        __nv_bfloat16 hi = __float2bfloat16(val);
        g_ahi[b * HID_ + h * D_ + tid] = hi;
        g_alo[b * HID_ + h * D_ + tid] = __float2bfloat16(val - __bfloat162float(hi));
    }
}

// ---------------------------------------------------------------------------
// Kernel 4: oproj split-bf16 WMMA, double-buffered, [n][k] staging (packed
// STS.64) + col_major B fragments. grid (32 i-tiles, KSPLITO=4).
// ---------------------------------------------------------------------------
__global__ __launch_bounds__(256) void oproj_wmma_kernel(const float* __restrict__ Wo) {
    __shared__ __align__(16) __nv_bfloat16 s_whi[2][128][40];   // [n][k]
    __shared__ __align__(16) __nv_bfloat16 s_wlo[2][128][40];
    __shared__ __align__(16) __nv_bfloat16 s_ahi[2][32][40];
    __shared__ __align__(16) __nv_bfloat16 s_alo[2][32][40];
    const int tid = threadIdx.x;
    const int wid = tid >> 5;
    const int i0  = blockIdx.x * 128;
    const int k0  = blockIdx.y * (HID_ / KSPLITO);   // 1024

    wmma::fragment<wmma::accumulator, 16, 16, 16, float> acc0, acc1;
    wmma::fill_fragment(acc0, 0.f);
    wmma::fill_fragment(acc1, 0.f);

    const __nv_bfloat16* asrc = (tid < 128) ? g_ahi : g_alo;
    const int ai   = tid & 127;
    const int arow = ai >> 2;
    const int acol = (ai & 3) * 8;
    const int wn   = tid >> 1;            // 0..127 : n index
    const int wk   = (tid & 1) * 16;      // 0 or 16 : k base (2 float4 per thread)

#define OSTAGE(BUF)                                                              \
    _Pragma("unroll")                                                            \
    for (int t = 0; t < 2; t++) {                                                \
        float4 w4 = wreg[t];                                                     \
        int kq = wk + t * 8;                                                     \
        unsigned hA = bfpack(w4.x, w4.y);                                        \
        unsigned hB = bfpack(w4.z, w4.w);                                        \
        unsigned lA = bfpack(w4.x - bflow(hA), w4.y - bfhigh(hA));               \
        unsigned lB = bfpack(w4.z - bflow(hB), w4.w - bfhigh(hB));               \
        *(uint2*)&s_whi[BUF][wn][kq] = make_uint2(hA, hB);                       \
        *(uint2*)&s_wlo[BUF][wn][kq] = make_uint2(lA, lB);                       \
        float4 w4b = wreg[t + 2];                                                \
        unsigned hC = bfpack(w4b.x, w4b.y);                                      \
        unsigned hD = bfpack(w4b.z, w4b.w);                                      \
        unsigned lC = bfpack(w4b.x - bflow(hC), w4b.y - bfhigh(hC));             \
        unsigned lD = bfpack(w4b.z - bflow(hD), w4b.w - bfhigh(hD));             \
        *(uint2*)&s_whi[BUF][wn][kq + 4] = make_uint2(hC, hD);                   \
        *(uint2*)&s_wlo[BUF][wn][kq + 4] = make_uint2(lC, lD);                   \
    }

    // thread covers row wn, k range [wk, wk+16): 4 float4
    float4 wreg[4];
#pragma unroll
    for (int t = 0; t < 4; t++)
        wreg[t] = *(const float4*)&Wo[(size_t)(i0 + wn) * HID_ + k0 + ((t & 1) ? wk + (t >> 1) * 8 + 4 : wk + (t >> 1) * 8)];
    // simpler: wreg[0]=k[wk..3], wreg[1]=k[wk+4..7]? redo deterministic:
#pragma unroll
    for (int t = 0; t < 4; t++)
        wreg[t] = *(const float4*)&Wo[(size_t)(i0 + wn) * HID_ + k0 + wk + t * 4];
    {
        uint4 areg = *(const uint4*)&asrc[arow * HID_ + k0 + acol];
        // stage: wreg[0..3] cover k wk..wk+15 contiguous
#pragma unroll
        for (int t = 0; t < 4; t++) {
            float4 w4 = wreg[t];
            int kq = wk + t * 4;
            unsigned hA = bfpack(w4.x, w4.y);
            unsigned hB = bfpack(w4.z, w4.w);
            unsigned lA = bfpack(w4.x - bflow(hA), w4.y - bfhigh(hA));
            unsigned lB = bfpack(w4.z - bflow(hB), w4.w - bfhigh(hB));
            *(uint2*)&s_whi[0][wn][kq] = make_uint2(hA, hB);
            *(uint2*)&s_wlo[0][wn][kq] = make_uint2(lA, lB);
        }
        if (tid < 128) *(uint4*)&s_ahi[0][arow][acol] = areg;
        else           *(uint4*)&s_alo[0][arow][acol] = areg;
    }
#pragma unroll
    for (int t = 0; t < 4; t++)
        wreg[t] = *(const float4*)&Wo[(size_t)(i0 + wn) * HID_ + k0 + 32 + wk + t * 4];
    __syncthreads();

    for (int ph = 0; ph < 32; ph++) {
        const int buf = ph & 1;
        const int nbf = buf ^ 1;
        if (ph < 31) {
            uint4 areg = *(const uint4*)&asrc[arow * HID_ + k0 + (ph + 1) * 32 + acol];
#pragma unroll
            for (int t = 0; t < 4; t++) {
                float4 w4 = wreg[t];
                int kq = wk + t * 4;
                unsigned hA = bfpack(w4.x, w4.y);
                unsigned hB = bfpack(w4.z, w4.w);
                unsigned lA = bfpack(w4.x - bflow(hA), w4.y - bfhigh(hA));
                unsigned lB = bfpack(w4.z - bflow(hB), w4.w - bfhigh(hB));
                *(uint2*)&s_whi[nbf][wn][kq] = make_uint2(hA, hB);
                *(uint2*)&s_wlo[nbf][wn][kq] = make_uint2(lA, lB);
            }
            if (tid < 128) *(uint4*)&s_ahi[nbf][arow][acol] = areg;
            else           *(uint4*)&s_alo[nbf][arow][acol] = areg;
            if (ph < 30) {
#pragma unroll
                for (int t = 0; t < 4; t++)
                    wreg[t] = *(const float4*)&Wo[(size_t)(i0 + wn) * HID_ + k0 + (ph + 2) * 32 + wk + t * 4];
            }
        }

#pragma unroll
        for (int kt = 0; kt < 2; kt++) {
            wmma::fragment<wmma::matrix_a, 16, 16, 16, __nv_bfloat16, wmma::row_major> ahi0, alo0, ahi1, alo1;
            wmma::fragment<wmma::matrix_b, 16, 16, 16, __nv_bfloat16, wmma::col_major> bhi, blo;
            wmma::load_matrix_sync(ahi0, &s_ahi[buf][0][kt * 16], 40);
            wmma::load_matrix_sync(ahi1, &s_ahi[buf][16][kt * 16], 40);
            wmma::load_matrix_sync(alo0, &s_alo[buf][0][kt * 16], 40);
            wmma::load_matrix_sync(alo1, &s_alo[buf][16][kt * 16], 40);
            wmma::load_matrix_sync(bhi, &s_whi[buf][wid * 16][kt * 16], 40);
            wmma::load_matrix_sync(blo, &s_wlo[buf][wid * 16][kt * 16], 40);
            wmma::mma_sync(acc0, ahi0, bhi, acc0);
            wmma::mma_sync(acc1, ahi1, bhi, acc1);
            wmma::mma_sync(acc0, alo0, bhi, acc0);
            wmma::mma_sync(acc1, alo1, bhi, acc1);
            wmma::mma_sync(acc0, ahi0, blo, acc0);
            wmma::mma_sync(acc1, ahi1, blo, acc1);
        }
        __syncthreads();
    }
#undef OSTAGE

    float* outp = &g_part[blockIdx.y][0];
    wmma::store_matrix_sync(&outp[i0 + wid * 16], acc0, HID_, wmma::mem_row_major);
    wmma::store_matrix_sync(&outp[(size_t)16 * HID_ + i0 + wid * 16], acc1, HID_, wmma::mem_row_major);
}

// Reduce KSPLITO oproj partials -> out.
__global__ __launch_bounds__(256) void oproj_reduce_kernel(float* __restrict__ out) {
    int i = (blockIdx.x * 256 + threadIdx.x) * 4;
    float4 r = *(const float4*)&g_part[0][i];
#pragma unroll
    for (int p = 1; p < KSPLITO; p++) {
        float4 a = *(const float4*)&g_part[p][i];
        r.x += a.x; r.y += a.y; r.z += a.z; r.w += a.w;
    }
    *(float4*)&out[i] = r;
}

// ---------------------------------------------------------------------------
extern "C" void kernel_launch(void* const* d_in, const int* in_sizes, int n_in,
                              void* d_out, int out_size) {
    const float* hidden = (const float*)d_in[0];
    const float* W      = (const float*)d_in[1];
    const float* Wo     = (const float*)d_in[2];
    const float* kcache = (const float*)d_in[3];
    const float* vcache = (const float*)d_in[4];
    const int*   hist   = (const int*)d_in[5];
    const int*   boff   = (const int*)d_in[6];
    float*       out    = (float*)d_out;

    hsplit_kernel<<<B_ * HID_ / 256, 256>>>(hidden, hist);
    qkv_wmma_kernel<<<dim3(TH_ / 128, KSPLIT), 256>>>(W);
    qkv_reduce_rope<<<256, 256>>>(0);
    attn_kernel<<<B_ * H_, 256>>>(kcache, vcache, hist, boff);
    oproj_wmma_kernel<<<dim3(HID_ / 128, KSPLITO), 256>>>(Wo);
    oproj_reduce_kernel<<<B_ * HID_ / 1024, 256>>>(out);
}

// round 16
// speedup vs baseline: 1.8575x; 1.0830x over previous
#include <cuda_runtime.h>
#include <cuda_bf16.h>
#include <mma.h>
#include <math.h>

using namespace nvcuda;

#define B_    32
#define H_    32
#define D_    128
#define HID_  4096
#define TH_   12288      // 3*HID
#define BS_   64
#define NBLK_ 16
#define KSPLIT 8
#define KSPLITO 4
#define NCHUNK 8         // split-KV chunks of 128 positions

__device__ float g_part[KSPLIT][B_ * TH_];  // qkv partials (reused by oproj)
__device__ float g_qkv[B_ * TH_];           // [b][j]; j<4096 q, ..8191 k, .. v
__device__ float g_cs[B_][64][2];           // rope cos/sin table
__device__ __nv_bfloat16 g_hhi[B_ * HID_];  // hidden split hi
__device__ __nv_bfloat16 g_hlo[B_ * HID_];  // hidden split lo
__device__ __nv_bfloat16 g_ahi[B_ * HID_];  // attn split hi
__device__ __nv_bfloat16 g_alo[B_ * HID_];  // attn split lo
__device__ float g_pm[NCHUNK][B_ * H_];     // partial max
__device__ float g_pl[NCHUNK][B_ * H_];     // partial sum
__device__ float g_pacc[NCHUNK][B_ * H_ * D_];  // partial acc (4 MB)

__device__ __forceinline__ unsigned bfpack(float f0, float f1) {
    __nv_bfloat162 p = __floats2bfloat162_rn(f0, f1);
    return *(unsigned*)&p;
}
__device__ __forceinline__ float bflow(unsigned w)  { return __uint_as_float(w << 16); }
__device__ __forceinline__ float bfhigh(unsigned w) { return __uint_as_float(w & 0xffff0000u); }

// ---------------------------------------------------------------------------
// Kernel 0: split hidden into bf16 hi/lo; blocks 0-31 also fill rope table.
// ---------------------------------------------------------------------------
__global__ __launch_bounds__(256) void hsplit_kernel(const float* __restrict__ hidden,
                                                     const int* __restrict__ hist) {
    int i = blockIdx.x * 256 + threadIdx.x;
    float x = hidden[i];
    __nv_bfloat16 hi = __float2bfloat16(x);
    g_hhi[i] = hi;
    g_hlo[i] = __float2bfloat16(x - __bfloat162float(hi));

    if (blockIdx.x < 32 && threadIdx.x < 64) {
        const int b = blockIdx.x;
        const int f = threadIdx.x;
        double invd = exp(-(double)f / 64.0 * 9.210340371976184);  // ln(10000)
        double angd = fmod((double)hist[b] * invd, 6.283185307179586476925286766559);
        g_cs[b][f][0] = cosf((float)angd);
        g_cs[b][f][1] = sinf((float)angd);
    }
}

// ---------------------------------------------------------------------------
// Kernel 1: qkv split-bf16 WMMA (R15). grid (96, KSPLIT=8), block 256.
// ---------------------------------------------------------------------------
__global__ __launch_bounds__(256) void qkv_wmma_kernel(const float* __restrict__ W) {
    __shared__ __align__(16) __nv_bfloat16 s_whi[2][32][136];
    __shared__ __align__(16) __nv_bfloat16 s_wlo[2][32][136];
    __shared__ __align__(16) __nv_bfloat16 s_ahi[2][32][40];
    __shared__ __align__(16) __nv_bfloat16 s_alo[2][32][40];
    const int tid = threadIdx.x;
    const int wid = tid >> 5;
    const int j0  = blockIdx.x * 128;
    const int k0  = blockIdx.y * (HID_ / KSPLIT);   // 512

    wmma::fragment<wmma::accumulator, 16, 16, 16, float> acc0, acc1;
    wmma::fill_fragment(acc0, 0.f);
    wmma::fill_fragment(acc1, 0.f);

    const float* wbase = W + j0;
    const __nv_bfloat16* asrc = (tid < 128) ? g_hhi : g_hlo;
    const int ai   = tid & 127;
    const int arow = ai >> 2;
    const int acol = (ai & 3) * 8;

#define QSTAGE(BUF)                                                              \
    _Pragma("unroll")                                                            \
    for (int t = 0; t < 4; t++) {                                                \
        int idx = tid + t * 256;                                                 \
        int row = idx >> 5;                                                      \
        int col = (idx & 31) * 4;                                                \
        float4 w4 = wreg[t];                                                     \
        unsigned hA = bfpack(w4.x, w4.y);                                        \
        unsigned hB = bfpack(w4.z, w4.w);                                        \
        unsigned lA = bfpack(w4.x - bflow(hA), w4.y - bfhigh(hA));               \
        unsigned lB = bfpack(w4.z - bflow(hB), w4.w - bfhigh(hB));               \
        *(uint2*)&s_whi[BUF][row][col] = make_uint2(hA, hB);                     \
        *(uint2*)&s_wlo[BUF][row][col] = make_uint2(lA, lB);                     \
    }

    float4 wreg[4];
#pragma unroll
    for (int t = 0; t < 4; t++) {
        int idx = tid + t * 256;
        wreg[t] = *(const float4*)&wbase[(size_t)(k0 + (idx >> 5)) * TH_ + (idx & 31) * 4];
    }
    {
        uint4 areg = *(const uint4*)&asrc[arow * HID_ + k0 + acol];
        QSTAGE(0)
        if (tid < 128) *(uint4*)&s_ahi[0][arow][acol] = areg;
        else           *(uint4*)&s_alo[0][arow][acol] = areg;
    }
#pragma unroll
    for (int t = 0; t < 4; t++) {
        int idx = tid + t * 256;
        wreg[t] = *(const float4*)&wbase[(size_t)(k0 + 32 + (idx >> 5)) * TH_ + (idx & 31) * 4];
    }
    __syncthreads();

    for (int ph = 0; ph < 16; ph++) {
        const int buf = ph & 1;
        const int nbf = buf ^ 1;
        if (ph < 15) {
            uint4 areg = *(const uint4*)&asrc[arow * HID_ + k0 + (ph + 1) * 32 + acol];
            if (nbf) { QSTAGE(1) } else { QSTAGE(0) }
            if (tid < 128) *(uint4*)&s_ahi[nbf][arow][acol] = areg;
            else           *(uint4*)&s_alo[nbf][arow][acol] = areg;
            if (ph < 14) {
#pragma unroll
                for (int t = 0; t < 4; t++) {
                    int idx = tid + t * 256;
                    wreg[t] = *(const float4*)&wbase[(size_t)(k0 + (ph + 2) * 32 + (idx >> 5)) * TH_ + (idx & 31) * 4];
                }
            }
        }

#pragma unroll
        for (int kt = 0; kt < 2; kt++) {
            wmma::fragment<wmma::matrix_a, 16, 16, 16, __nv_bfloat16, wmma::row_major> ahi0, alo0, ahi1, alo1;
            wmma::fragment<wmma::matrix_b, 16, 16, 16, __nv_bfloat16, wmma::row_major> bhi, blo;
            wmma::load_matrix_sync(ahi0, &s_ahi[buf][0][kt * 16], 40);
            wmma::load_matrix_sync(ahi1, &s_ahi[buf][16][kt * 16], 40);
            wmma::load_matrix_sync(alo0, &s_alo[buf][0][kt * 16], 40);
            wmma::load_matrix_sync(alo1, &s_alo[buf][16][kt * 16], 40);
            wmma::load_matrix_sync(bhi, &s_whi[buf][kt * 16][wid * 16], 136);
            wmma::load_matrix_sync(blo, &s_wlo[buf][kt * 16][wid * 16], 136);
            wmma::mma_sync(acc0, ahi0, bhi, acc0);
            wmma::mma_sync(acc1, ahi1, bhi, acc1);
            wmma::mma_sync(acc0, alo0, bhi, acc0);
            wmma::mma_sync(acc1, alo1, bhi, acc1);
            wmma::mma_sync(acc0, ahi0, blo, acc0);
            wmma::mma_sync(acc1, ahi1, blo, acc1);
        }
        __syncthreads();
    }
#undef QSTAGE

    float* outp = &g_part[blockIdx.y][0];
    wmma::store_matrix_sync(&outp[j0 + wid * 16], acc0, TH_, wmma::mem_row_major);
    wmma::store_matrix_sync(&outp[(size_t)16 * TH_ + j0 + wid * 16], acc1, TH_, wmma::mem_row_major);
}

// ---------------------------------------------------------------------------
// Kernel 2: reduce KSPLIT partials + apply RoPE inline. grid 256 x 256.
// ---------------------------------------------------------------------------
__global__ __launch_bounds__(256) void qkv_reduce_rope(int dummy) {
    const int t = blockIdx.x * 256 + threadIdx.x;
    if (t < 32768) {
        const int b    = t >> 10;
        const int rem  = t & 1023;
        const int part = rem >> 9;
        const int rem2 = rem & 511;
        const int h    = rem2 >> 4;
        const int dq   = rem2 & 15;
        const int d0   = dq * 4;
        const int idx_lo = b * TH_ + part * HID_ + h * D_ + d0;
        const int idx_hi = idx_lo + 64;

        float4 rl = *(const float4*)&g_part[0][idx_lo];
        float4 rh = *(const float4*)&g_part[0][idx_hi];
#pragma unroll
        for (int p = 1; p < KSPLIT; p++) {
            float4 a = *(const float4*)&g_part[p][idx_lo];
            float4 c = *(const float4*)&g_part[p][idx_hi];
            rl.x += a.x; rl.y += a.y; rl.z += a.z; rl.w += a.w;
            rh.x += c.x; rh.y += c.y; rh.z += c.z; rh.w += c.w;
        }
        float4 cs0 = *(const float4*)&g_cs[b][d0][0];
        float4 cs1 = *(const float4*)&g_cs[b][d0 + 2][0];
        float4 ol, oh;
        ol.x = rl.x * cs0.x - rh.x * cs0.y;  oh.x = rh.x * cs0.x + rl.x * cs0.y;
        ol.y = rl.y * cs0.z - rh.y * cs0.w;  oh.y = rh.y * cs0.z + rl.y * cs0.w;
        ol.z = rl.z * cs1.x - rh.z * cs1.y;  oh.z = rh.z * cs1.x + rl.z * cs1.y;
        ol.w = rl.w * cs1.z - rh.w * cs1.w;  oh.w = rh.w * cs1.z + rl.w * cs1.w;
        *(float4*)&g_qkv[idx_lo] = ol;
        *(float4*)&g_qkv[idx_hi] = oh;
    } else {
        const int t2  = t - 32768;
        const int b   = t2 >> 10;
        const int off = (t2 & 1023) * 4;
        const int idx = b * TH_ + 2 * HID_ + off;
        float4 r = *(const float4*)&g_part[0][idx];
#pragma unroll
        for (int p = 1; p < KSPLIT; p++) {
            float4 a = *(const float4*)&g_part[p][idx];
            r.x += a.x; r.y += a.y; r.z += a.z; r.w += a.w;
        }
        *(float4*)&g_qkv[idx] = r;
    }
}

// ---------------------------------------------------------------------------
// Kernel 3a: split-KV attention partials. grid (B*H, NCHUNK), 256 threads.
// Chunk = 128 positions -> uniform work per block (multi-wave balance).
// ---------------------------------------------------------------------------
__global__ __launch_bounds__(256) void attn_part_kernel(const float* __restrict__ kcache,
                                                        const float* __restrict__ vcache,
                                                        const int* __restrict__ hist,
                                                        const int* __restrict__ boff) {
    const int bh = blockIdx.x;
    const int c  = blockIdx.y;
    const int b  = bh >> 5;
    const int h  = bh & 31;
    const int tid  = threadIdx.x;
    const int lane = tid & 31;
    const int wid  = tid >> 5;

    const int pos  = hist[b];
    const int base = c * 128;
    if (base > pos) return;                     // chunk beyond history: no work
    const int cachedLen = min(128, pos - base); // positions with s < pos
    const bool hasFresh = (pos - base) < 128;   // s == pos lands in this chunk

    __shared__ int   s_blk[NBLK_];
    __shared__ float s_sc[128];
    __shared__ float s_red[8];
    __shared__ float s_acc[8][128];

    if (tid < NBLK_) s_blk[tid] = boff[b * NBLK_ + tid];
    __syncthreads();

    const float scale = 0.08838834764831845f;   // 1/sqrt(128)
    const float4 q4 = *(const float4*)&g_qkv[b * TH_ + h * D_ + lane * 4];

    // ---- phase 1: scores ----
    float mloc = -1e30f;
    int j = wid;
    for (; j + 56 < cachedLen; j += 64) {
        float4 k[8];
#pragma unroll
        for (int u = 0; u < 8; u++) {
            int s = base + j + u * 8;
            int a = ((s_blk[s >> 6] * BS_ + (s & 63)) * H_ + h) * D_;
            k[u] = *(const float4*)&kcache[a + lane * 4];
        }
        float dt[8];
#pragma unroll
        for (int u = 0; u < 8; u++)
            dt[u] = q4.x * k[u].x + q4.y * k[u].y + q4.z * k[u].z + q4.w * k[u].w;
#pragma unroll
        for (int o = 16; o > 0; o >>= 1)
#pragma unroll
            for (int u = 0; u < 8; u++)
                dt[u] += __shfl_xor_sync(0xffffffffu, dt[u], o);
#pragma unroll
        for (int u = 0; u < 8; u++) {
            dt[u] *= scale;
            mloc = fmaxf(mloc, dt[u]);
            if (lane == 0) s_sc[j + u * 8] = dt[u];
        }
    }
    for (; j < cachedLen; j += 8) {
        int s = base + j;
        int a = ((s_blk[s >> 6] * BS_ + (s & 63)) * H_ + h) * D_;
        float4 k0 = *(const float4*)&kcache[a + lane * 4];
        float d0 = q4.x * k0.x + q4.y * k0.y + q4.z * k0.z + q4.w * k0.w;
#pragma unroll
        for (int o = 16; o > 0; o >>= 1) d0 += __shfl_xor_sync(0xffffffffu, d0, o);
        d0 *= scale;
        mloc = fmaxf(mloc, d0);
        if (lane == 0) s_sc[j] = d0;
    }
    if (hasFresh && ((pos - base) & 7) == wid) {   // fresh k at s == pos
        const float* kp = &g_qkv[b * TH_ + HID_ + h * D_];
        float4 k0 = *(const float4*)&kp[lane * 4];
        float d0 = q4.x * k0.x + q4.y * k0.y + q4.z * k0.z + q4.w * k0.w;
#pragma unroll
        for (int o = 16; o > 0; o >>= 1) d0 += __shfl_xor_sync(0xffffffffu, d0, o);
        d0 *= scale;
        mloc = fmaxf(mloc, d0);
        if (lane == 0) s_sc[pos - base] = d0;
    }

    if (lane == 0) s_red[wid] = mloc;
    __syncthreads();
    float M = -1e30f;
#pragma unroll
    for (int w = 0; w < 8; w++) M = fmaxf(M, s_red[w]);

    const int cnt = cachedLen + (hasFresh ? 1 : 0);
    float lsum = 0.f;
    if (tid < cnt) {                     // cnt <= 129... cnt <= 128+1? no: <=128
        float p = __expf(s_sc[tid] - M);
        s_sc[tid] = p;
        lsum = p;
    }
#pragma unroll
    for (int o = 16; o > 0; o >>= 1) lsum += __shfl_xor_sync(0xffffffffu, lsum, o);
    __syncthreads();
    if (lane == 0) s_red[wid] = lsum;
    __syncthreads();
    float Lc = 0.f;
#pragma unroll
    for (int w = 0; w < 8; w++) Lc += s_red[w];

    // ---- phase 2: V stream ----
    float4 a4 = make_float4(0.f, 0.f, 0.f, 0.f);
    j = wid;
    for (; j + 56 < cachedLen; j += 64) {
        float4 v[8];
        float  pr[8];
#pragma unroll
        for (int u = 0; u < 8; u++) {
            int s = base + j + u * 8;
            int a = ((s_blk[s >> 6] * BS_ + (s & 63)) * H_ + h) * D_;
            v[u]  = *(const float4*)&vcache[a + lane * 4];
            pr[u] = s_sc[j + u * 8];
        }
#pragma unroll
        for (int u = 0; u < 8; u++) {
            a4.x += pr[u] * v[u].x;
            a4.y += pr[u] * v[u].y;
            a4.z += pr[u] * v[u].z;
            a4.w += pr[u] * v[u].w;
        }
    }
    for (; j < cachedLen; j += 8) {
        int s = base + j;
        int a = ((s_blk[s >> 6] * BS_ + (s & 63)) * H_ + h) * D_;
        float4 v = *(const float4*)&vcache[a + lane * 4];
        float  p = s_sc[j];
        a4.x += p * v.x; a4.y += p * v.y; a4.z += p * v.z; a4.w += p * v.w;
    }
    if (hasFresh && ((pos - base) & 7) == wid) {   // fresh v at s == pos
        const float* vp = &g_qkv[b * TH_ + 2 * HID_ + h * D_];
        float4 v = *(const float4*)&vp[lane * 4];
        float  p = s_sc[pos - base];
        a4.x += p * v.x; a4.y += p * v.y; a4.z += p * v.z; a4.w += p * v.w;
    }

    *(float4*)&s_acc[wid][lane * 4] = a4;
    __syncthreads();
    if (tid < 128) {
        float val = 0.f;
#pragma unroll
        for (int w = 0; w < 8; w++) val += s_acc[w][tid];
        g_pacc[c][bh * D_ + tid] = val;
    }
    if (tid == 0) { g_pm[c][bh] = M; g_pl[c][bh] = Lc; }
}

// ---------------------------------------------------------------------------
// Kernel 3b: combine partials -> attn, write bf16 hi/lo. grid B*H, 128 thr.
// ---------------------------------------------------------------------------
__global__ __launch_bounds__(128) void attn_combine_kernel(const int* __restrict__ hist) {
    const int bh = blockIdx.x;
    const int b  = bh >> 5;
    const int h  = bh & 31;
    const int tid = threadIdx.x;
    const int pos = hist[b];
    const int nc  = (pos >> 7) + 1;

    __shared__ float sm[NCHUNK], sl[NCHUNK];
    if (tid < nc) { sm[tid] = g_pm[tid][bh]; sl[tid] = g_pl[tid][bh]; }
    __syncthreads();

    float M = -1e30f;
    for (int c = 0; c < nc; c++) M = fmaxf(M, sm[c]);
    float L = 0.f, val = 0.f;
    for (int c = 0; c < nc; c++) {
        float r = __expf(sm[c] - M);
        L   += sl[c] * r;
        val += g_pacc[c][bh * D_ + tid] * r;
    }
    val /= L;
    __nv_bfloat16 hi = __float2bfloat16(val);
    g_ahi[b * HID_ + h * D_ + tid] = hi;
    g_alo[b * HID_ + h * D_ + tid] = __float2bfloat16(val - __bfloat162float(hi));
}

// ---------------------------------------------------------------------------
// Kernel 4: oproj split-bf16 WMMA (R15). grid (32, KSPLITO=4), block 256.
// ---------------------------------------------------------------------------
__global__ __launch_bounds__(256) void oproj_wmma_kernel(const float* __restrict__ Wo) {
    __shared__ __align__(16) __nv_bfloat16 s_whi[2][128][40];   // [n][k]
    __shared__ __align__(16) __nv_bfloat16 s_wlo[2][128][40];
    __shared__ __align__(16) __nv_bfloat16 s_ahi[2][32][40];
    __shared__ __align__(16) __nv_bfloat16 s_alo[2][32][40];
    const int tid = threadIdx.x;
    const int wid = tid >> 5;
    const int i0  = blockIdx.x * 128;
    const int k0  = blockIdx.y * (HID_ / KSPLITO);   // 1024

    wmma::fragment<wmma::accumulator, 16, 16, 16, float> acc0, acc1;
    wmma::fill_fragment(acc0, 0.f);
    wmma::fill_fragment(acc1, 0.f);

    const __nv_bfloat16* asrc = (tid < 128) ? g_ahi : g_alo;
    const int ai   = tid & 127;
    const int arow = ai >> 2;
    const int acol = (ai & 3) * 8;
    const int wn   = tid >> 1;
    const int wk   = (tid & 1) * 16;

    float4 wreg[4];
#pragma unroll
    for (int t = 0; t < 4; t++)
        wreg[t] = *(const float4*)&Wo[(size_t)(i0 + wn) * HID_ + k0 + wk + t * 4];
    {
        uint4 areg = *(const uint4*)&asrc[arow * HID_ + k0 + acol];
#pragma unroll
        for (int t = 0; t < 4; t++) {
            float4 w4 = wreg[t];
            int kq = wk + t * 4;
            unsigned hA = bfpack(w4.x, w4.y);
            unsigned hB = bfpack(w4.z, w4.w);
            unsigned lA = bfpack(w4.x - bflow(hA), w4.y - bfhigh(hA));
            unsigned lB = bfpack(w4.z - bflow(hB), w4.w - bfhigh(hB));
            *(uint2*)&s_whi[0][wn][kq] = make_uint2(hA, hB);
            *(uint2*)&s_wlo[0][wn][kq] = make_uint2(lA, lB);
        }
        if (tid < 128) *(uint4*)&s_ahi[0][arow][acol] = areg;
        else           *(uint4*)&s_alo[0][arow][acol] = areg;
    }
#pragma unroll
    for (int t = 0; t < 4; t++)
        wreg[t] = *(const float4*)&Wo[(size_t)(i0 + wn) * HID_ + k0 + 32 + wk + t * 4];
    __syncthreads();

    for (int ph = 0; ph < 32; ph++) {
        const int buf = ph & 1;
        const int nbf = buf ^ 1;
        if (ph < 31) {
            uint4 areg = *(const uint4*)&asrc[arow * HID_ + k0 + (ph + 1) * 32 + acol];
#pragma unroll
            for (int t = 0; t < 4; t++) {
                float4 w4 = wreg[t];
                int kq = wk + t * 4;
                unsigned hA = bfpack(w4.x, w4.y);
                unsigned hB = bfpack(w4.z, w4.w);
                unsigned lA = bfpack(w4.x - bflow(hA), w4.y - bfhigh(hA));
                unsigned lB = bfpack(w4.z - bflow(hB), w4.w - bfhigh(hB));
                *(uint2*)&s_whi[nbf][wn][kq] = make_uint2(hA, hB);
                *(uint2*)&s_wlo[nbf][wn][kq] = make_uint2(lA, lB);
            }
            if (tid < 128) *(uint4*)&s_ahi[nbf][arow][acol] = areg;
            else           *(uint4*)&s_alo[nbf][arow][acol] = areg;
            if (ph < 30) {
#pragma unroll
                for (int t = 0; t < 4; t++)
                    wreg[t] = *(const float4*)&Wo[(size_t)(i0 + wn) * HID_ + k0 + (ph + 2) * 32 + wk + t * 4];
            }
        }

#pragma unroll
        for (int kt = 0; kt < 2; kt++) {
            wmma::fragment<wmma::matrix_a, 16, 16, 16, __nv_bfloat16, wmma::row_major> ahi0, alo0, ahi1, alo1;
            wmma::fragment<wmma::matrix_b, 16, 16, 16, __nv_bfloat16, wmma::col_major> bhi, blo;
            wmma::load_matrix_sync(ahi0, &s_ahi[buf][0][kt * 16], 40);
            wmma::load_matrix_sync(ahi1, &s_ahi[buf][16][kt * 16], 40);
            wmma::load_matrix_sync(alo0, &s_alo[buf][0][kt * 16], 40);
            wmma::load_matrix_sync(alo1, &s_alo[buf][16][kt * 16], 40);
            wmma::load_matrix_sync(bhi, &s_whi[buf][wid * 16][kt * 16], 40);
            wmma::load_matrix_sync(blo, &s_wlo[buf][wid * 16][kt * 16], 40);
            wmma::mma_sync(acc0, ahi0, bhi, acc0);
            wmma::mma_sync(acc1, ahi1, bhi, acc1);
            wmma::mma_sync(acc0, alo0, bhi, acc0);
            wmma::mma_sync(acc1, alo1, bhi, acc1);
            wmma::mma_sync(acc0, ahi0, blo, acc0);
            wmma::mma_sync(acc1, ahi1, blo, acc1);
        }
        __syncthreads();
    }

    float* outp = &g_part[blockIdx.y][0];
    wmma::store_matrix_sync(&outp[i0 + wid * 16], acc0, HID_, wmma::mem_row_major);
    wmma::store_matrix_sync(&outp[(size_t)16 * HID_ + i0 + wid * 16], acc1, HID_, wmma::mem_row_major);
}

// Reduce KSPLITO oproj partials -> out.
__global__ __launch_bounds__(256) void oproj_reduce_kernel(float* __restrict__ out) {
    int i = (blockIdx.x * 256 + threadIdx.x) * 4;
    float4 r = *(const float4*)&g_part[0][i];
#pragma unroll
    for (int p = 1; p < KSPLITO; p++) {
        float4 a = *(const float4*)&g_part[p][i];
        r.x += a.x; r.y += a.y; r.z += a.z; r.w += a.w;
    }
    *(float4*)&out[i] = r;
}

// ---------------------------------------------------------------------------
extern "C" void kernel_launch(void* const* d_in, const int* in_sizes, int n_in,
                              void* d_out, int out_size) {
    const float* hidden = (const float*)d_in[0];
    const float* W      = (const float*)d_in[1];
    const float* Wo     = (const float*)d_in[2];
    const float* kcache = (const float*)d_in[3];
    const float* vcache = (const float*)d_in[4];
    const int*   hist   = (const int*)d_in[5];
    const int*   boff   = (const int*)d_in[6];
    float*       out    = (float*)d_out;

    hsplit_kernel<<<B_ * HID_ / 256, 256>>>(hidden, hist);
    qkv_wmma_kernel<<<dim3(TH_ / 128, KSPLIT), 256>>>(W);
    qkv_reduce_rope<<<256, 256>>>(0);
    attn_part_kernel<<<dim3(B_ * H_, NCHUNK), 256>>>(kcache, vcache, hist, boff);
    attn_combine_kernel<<<B_ * H_, 128>>>(hist);
    oproj_wmma_kernel<<<dim3(HID_ / 128, KSPLITO), 256>>>(Wo);
    oproj_reduce_kernel<<<B_ * HID_ / 1024, 256>>>(out);
}